// round 14
// baseline (speedup 1.0000x reference)
#include <cuda_runtime.h>
#include <cuda_bf16.h>
#include <cuda_fp16.h>
#include <cstdint>

// ---------------- problem constants ----------------
#define B_WIN  2048
#define NTOK   49
#define DIMF   256
#define HEADS  8
#define HD     32
#define MROWS  (B_WIN * NTOK)        // 100352
#define QKVCOL 768

#define LOSC   2048.0f               // GEMM lo-term pre-scale
#define LOINV  4.8828125e-4f         // 1/2048
#define PSC    512.0f                // attn P-lo pre-scale
#define PSCINV 1.953125e-3f          // 1/512

// ---------------- scratch ----------------
__device__ float g_qkv [MROWS * QKVCOL];
__device__ float g_attn[MROWS * DIMF];      // used as __half buffer (half of it)
__device__ float g_bias[HEADS * 64 * 56];   // padded [8][64][56]; pads stay 0
__device__ float g_scale[HEADS];
__device__ unsigned char g_wq[48 * 16384];  // fp16 hi/lo chunks
__device__ unsigned char g_wp[16 * 16384];

// ---------------- helpers ----------------
static __device__ __forceinline__ uint32_t s2u(const void* p) {
    uint32_t a;
    asm("{ .reg .u64 t; cvta.to.shared.u64 t, %1; cvt.u32.u64 %0, t; }" : "=r"(a) : "l"(p));
    return a;
}
static __device__ __forceinline__ uint32_t swz(uint32_t byte_in_row, uint32_t row) {
    return (byte_in_row & ~0x7Fu) | ((byte_in_row & 0x7Fu) ^ ((row & 7u) << 4));
}
static __device__ __forceinline__ uint32_t swz64(uint32_t c, uint32_t row) {
    return (c & 0xFu) | (((((c >> 4) ^ ((row >> 1) & 3u))) & 3u) << 4);
}

#define LDSM_X4(r, a)                                                        \
    asm volatile("ldmatrix.sync.aligned.m8n8.x4.shared.b16 {%0,%1,%2,%3}, [%4];" \
        : "=r"((r)[0]), "=r"((r)[1]), "=r"((r)[2]), "=r"((r)[3]) : "r"(a))
#define LDSM_X4T(r, a)                                                       \
    asm volatile("ldmatrix.sync.aligned.m8n8.x4.trans.shared.b16 {%0,%1,%2,%3}, [%4];" \
        : "=r"((r)[0]), "=r"((r)[1]), "=r"((r)[2]), "=r"((r)[3]) : "r"(a))

#define MMA_BF(c, a, b)                                                      \
    asm volatile("mma.sync.aligned.m16n8k16.row.col.f32.bf16.bf16.f32 "      \
        "{%0,%1,%2,%3}, {%4,%5,%6,%7}, {%8,%9}, {%0,%1,%2,%3};"              \
        : "+f"((c)[0]), "+f"((c)[1]), "+f"((c)[2]), "+f"((c)[3])             \
        : "r"((a)[0]), "r"((a)[1]), "r"((a)[2]), "r"((a)[3]),                \
          "r"((b)[0]), "r"((b)[1]))
#define MMA_FH(c, a, b)                                                      \
    asm volatile("mma.sync.aligned.m16n8k16.row.col.f32.f16.f16.f32 "        \
        "{%0,%1,%2,%3}, {%4,%5,%6,%7}, {%8,%9}, {%0,%1,%2,%3};"              \
        : "+f"((c)[0]), "+f"((c)[1]), "+f"((c)[2]), "+f"((c)[3])             \
        : "r"((a)[0]), "r"((a)[1]), "r"((a)[2]), "r"((a)[3]),                \
          "r"((b)[0]), "r"((b)[1]))
#define MMA_HH(c2, a, b)                                                     \
    asm volatile("mma.sync.aligned.m16n8k16.row.col.f16.f16.f16.f16 "        \
        "{%0,%1}, {%2,%3,%4,%5}, {%6,%7}, {%0,%1};"                          \
        : "+r"((c2)[0]), "+r"((c2)[1])                                       \
        : "r"((a)[0]), "r"((a)[1]), "r"((a)[2]), "r"((a)[3]),                \
          "r"((b)[0]), "r"((b)[1]))

#define CP16(d, s) \
    asm volatile("cp.async.cg.shared.global [%0], [%1], 16;" :: "r"(d), "l"(s) : "memory")
#define CP_COMMIT() asm volatile("cp.async.commit_group;" ::: "memory")
#define CP_WAIT(n)  asm volatile("cp.async.wait_group %0;" :: "n"(n) : "memory")

static __device__ __forceinline__ uint32_t pk2(float x, float y) {   // bf16x2
    uint32_t r;
    asm("cvt.rn.bf16x2.f32 %0, %1, %2;" : "=r"(r) : "f"(y), "f"(x));
    return r;
}
static __device__ __forceinline__ uint32_t pk2h(float x, float y) {  // f16x2
    uint32_t r;
    asm("cvt.rn.f16x2.f32 %0, %1, %2;" : "=r"(r) : "f"(y), "f"(x));
    return r;
}
static __device__ __forceinline__ float rbf(float x) {
    return __bfloat162float(__float2bfloat16_rn(x));
}
static __device__ __forceinline__ float rhf(float x) {
    return __half2float(__float2half_rn(x));
}

// =====================================================================
// Kernel 1: CPB-MLP bias table + logit scale
// =====================================================================
__device__ __forceinline__ float cpb_coord(int i) {
    float x = (float)(i - 6) * (8.0f / 6.0f);
    return copysignf(log1pf(fabsf(x)) * 0.4808983469629878f, x);
}

__global__ void cpb_kernel(const float* __restrict__ logit_scale,
                           const float* __restrict__ w1,
                           const float* __restrict__ b1,
                           const float* __restrict__ w2,
                           float* __restrict__ bias_out,
                           float* __restrict__ scale_out)
{
    __shared__ float table[169][HEADS];
    const int tid = threadIdx.x;

    if (tid < HEADS) {
        float ls = logit_scale[tid];
        ls = fminf(ls, logf(100.0f));
        ls = fmaxf(ls, -100.0f);
        scale_out[tid] = expf(ls);
    }
    for (int e = tid; e < 169; e += blockDim.x) {
        const int i = e / 13, j = e % 13;
        const float c0 = cpb_coord(i);
        const float c1 = cpb_coord(j);
        float acc[HEADS];
#pragma unroll
        for (int hh = 0; hh < HEADS; hh++) acc[hh] = 0.0f;
        for (int kk = 0; kk < 512; kk++) {
            float hpre = c0 * w1[kk] + c1 * w1[512 + kk] + b1[kk];
            float g = 0.5f * hpre * (1.0f + erff(hpre * 0.7071067811865475f));
#pragma unroll
            for (int hh = 0; hh < HEADS; hh++) acc[hh] += g * w2[kk * 8 + hh];
        }
#pragma unroll
        for (int hh = 0; hh < HEADS; hh++) table[e][hh] = acc[hh];
    }
    __syncthreads();

    for (int idx = tid; idx < HEADS * NTOK * NTOK; idx += blockDim.x) {
        const int hh  = idx / (NTOK * NTOK);
        const int rem = idx % (NTOK * NTOK);
        const int r   = rem / NTOK;
        const int c   = rem % NTOK;
        const int dh  = (r / 7) - (c / 7) + 6;
        const int dw  = (r % 7) - (c % 7) + 6;
        const float v = table[dh * 13 + dw][hh];
        bias_out[hh * 3584 + r * 56 + c] = 16.0f / (1.0f + __expf(-v));
    }
}

// =====================================================================
// Kernel 1b: split weights fp32 -> hi/lo fp16 chunks (lo pre-scaled x2048)
// =====================================================================
__global__ void wsplit_kernel(const float* __restrict__ wq, const float* __restrict__ wp,
                              unsigned char* __restrict__ oq, unsigned char* __restrict__ op)
{
    const int stride = gridDim.x * blockDim.x;
    const int t0 = blockIdx.x * blockDim.x + threadIdx.x;
    for (int idx = t0; idx < 256 * QKVCOL; idx += stride) {
        const int k = idx / QKVCOL, n = idx % QKVCOL;
        float f = wq[idx];
        __half h = __float2half_rn(f);
        __half l = __float2half_rn((f - __half2float(h)) * LOSC);
        const uint32_t off = (uint32_t)((n >> 7) * 8 + (k >> 5)) * 16384u
                           + (uint32_t)(k & 31) * 256u + swz((uint32_t)(n & 127) * 2u, (uint32_t)k);
        *(__half*)(oq + off)        = h;
        *(__half*)(oq + off + 8192) = l;
    }
    for (int idx = t0; idx < 256 * 256; idx += stride) {
        const int k = idx >> 8, n = idx & 255;
        float f = wp[idx];
        __half h = __float2half_rn(f);
        __half l = __float2half_rn((f - __half2float(h)) * LOSC);
        const uint32_t off = (uint32_t)((n >> 7) * 8 + (k >> 5)) * 16384u
                           + (uint32_t)(k & 31) * 256u + swz((uint32_t)(n & 127) * 2u, (uint32_t)k);
        *(__half*)(op + off)        = h;
        *(__half*)(op + off + 8192) = l;
    }
}

// =====================================================================
// Kernel 2: fp16 GEMM, single-sync 4-stage pipeline (unchanged R13).
// =====================================================================
#define SMW_OFF 32768
#define GEMM_SMEM (32768 + 4 * 16384)

template<bool AHALF, int NPROD>
__global__ __launch_bounds__(256, 2)
void gemm_mma(const void* __restrict__ Ain, const unsigned char* __restrict__ Wp,
              const float* __restrict__ bias, float* __restrict__ C, int NT)
{
    extern __shared__ char smem[];
    const uint32_t sb = s2u(smem);
    const int tid  = threadIdx.x;
    const int lane = tid & 31;
    const int w    = tid >> 5;
    const int row0 = blockIdx.x * 64;
    const int Ncols = NT * 128;
    constexpr int NCP = (NPROD == 2) ? 4 : 2;

    if (AHALF) {
        const __half* A16 = (const __half*)Ain;
        for (int i = tid; i < 2048; i += 256) {
            const int r  = i >> 5;
            const int c8 = (i & 31) << 3;
            uint4 v = *(const uint4*)(A16 + (size_t)(row0 + r) * 256 + c8);
            const uint32_t off = (uint32_t)r * 512u + swz((uint32_t)c8 * 2u, (uint32_t)r);
            *(uint4*)(smem + off) = v;
        }
    } else {
        const float* A = (const float*)Ain;
        for (int i = tid; i < 4096; i += 256) {
            const int r  = i >> 6;
            const int c4 = (i & 63) << 2;
            float4 a = *(const float4*)(A + (size_t)(row0 + r) * 256 + c4);
            const uint32_t off = (uint32_t)r * 512u + swz((uint32_t)c4 * 2u, (uint32_t)r);
            uint2 hu; hu.x = pk2h(a.x, a.y); hu.y = pk2h(a.z, a.w);
            *(uint2*)(smem + off) = hu;
        }
    }

    const int wm = w & 1;
    const int wn = w >> 1;
    const int NCH = NT * 8;

#pragma unroll
    for (int pf = 0; pf < 3; pf++) {
        const unsigned char* src = Wp + (size_t)pf * 16384;
        const uint32_t dst = sb + SMW_OFF + (uint32_t)pf * 16384u;
#pragma unroll
        for (int j = 0; j < NCP; j++)
            CP16(dst + (uint32_t)(tid * 16 + j * 4096), src + tid * 16 + j * 4096);
        CP_COMMIT();
    }
    __syncthreads();

    float    acc [2][4][4];
    uint32_t acch[2][4][2];
    int nt = 0;
#pragma unroll
    for (int mf = 0; mf < 2; mf++)
#pragma unroll
        for (int nf = 0; nf < 4; nf++) {
#pragma unroll
            for (int q = 0; q < 4; q++) acc[mf][nf][q] = 0.0f;
            acch[mf][nf][0] = 0u; acch[mf][nf][1] = 0u;
        }

    for (int gc = 0; gc < NCH; gc++) {
        CP_WAIT(2);
        __syncthreads();

        if (gc + 3 < NCH) {
            const unsigned char* src = Wp + (size_t)(gc + 3) * 16384;
            const uint32_t dst = sb + SMW_OFF + (uint32_t)(((gc + 3) & 3) * 16384);
#pragma unroll
            for (int j = 0; j < NCP; j++)
                CP16(dst + (uint32_t)(tid * 16 + j * 4096), src + tid * 16 + j * 4096);
        }
        CP_COMMIT();

        const uint32_t st = sb + SMW_OFF + (uint32_t)((gc & 3) * 16384);
        const int kc = gc & 7;

#pragma unroll
        for (int ks = 0; ks < 2; ks++) {
            uint32_t ah[2][4];
            const int arow = wm * 32 + ((lane >> 3) & 1) * 8 + (lane & 7);
            const int kg   = kc * 32 + ks * 16 + ((lane >> 4) << 3);
#pragma unroll
            for (int mf = 0; mf < 2; mf++) {
                const uint32_t r = (uint32_t)(arow + mf * 16);
                LDSM_X4(ah[mf], sb + r * 512u + swz((uint32_t)kg * 2u, r));
            }
            uint32_t bh[2][4], bl[2][4];
            const uint32_t krow = (uint32_t)(ks * 16 + ((lane >> 3) & 1) * 8 + (lane & 7));
#pragma unroll
            for (int nf2 = 0; nf2 < 2; nf2++) {
                const uint32_t ncol = (uint32_t)(wn * 32 + nf2 * 16 + (lane >> 4) * 8);
                const uint32_t addr = st + krow * 256u + swz(ncol * 2u, krow);
                LDSM_X4T(bh[nf2], addr);
                if (NPROD == 2) LDSM_X4T(bl[nf2], addr + 8192u);
            }
#pragma unroll
            for (int mf = 0; mf < 2; mf++)
#pragma unroll
                for (int nf = 0; nf < 4; nf++) {
                    uint32_t* bph = &bh[nf >> 1][(nf & 1) * 2];
                    MMA_FH(acc[mf][nf], ah[mf], bph);
                    if (NPROD == 2) {
                        uint32_t* bpl = &bl[nf >> 1][(nf & 1) * 2];
                        MMA_HH(acch[mf][nf], ah[mf], bpl);
                    }
                }
        }

        if (kc == 7) {
            const int g = lane >> 2, t = lane & 3;
#pragma unroll
            for (int nf = 0; nf < 4; nf++) {
                const int col = nt * 128 + wn * 32 + nf * 8 + t * 2;
                const float2 bv = *(const float2*)(bias + col);
#pragma unroll
                for (int mf = 0; mf < 2; mf++) {
                    const int row = row0 + wm * 32 + mf * 16 + g;
                    float lo0 = 0.f, lo1 = 0.f, lo2 = 0.f, lo3 = 0.f;
                    if (NPROD == 2) {
                        float2 c01 = __half22float2(*(const __half2*)&acch[mf][nf][0]);
                        float2 c23 = __half22float2(*(const __half2*)&acch[mf][nf][1]);
                        lo0 = c01.x * LOINV; lo1 = c01.y * LOINV;
                        lo2 = c23.x * LOINV; lo3 = c23.y * LOINV;
                    }
                    float2 v0 = make_float2(acc[mf][nf][0] + lo0 + bv.x,
                                            acc[mf][nf][1] + lo1 + bv.y);
                    float2 v1 = make_float2(acc[mf][nf][2] + lo2 + bv.x,
                                            acc[mf][nf][3] + lo3 + bv.y);
                    *(float2*)(C + (size_t)row * Ncols + col)       = v0;
                    *(float2*)(C + (size_t)(row + 8) * Ncols + col) = v1;
                }
            }
            nt++;
#pragma unroll
            for (int mf = 0; mf < 2; mf++)
#pragma unroll
                for (int nf = 0; nf < 4; nf++) {
#pragma unroll
                    for (int q = 0; q < 4; q++) acc[mf][nf][q] = 0.0f;
                    acch[mf][nf][0] = 0u; acch[mf][nf][1] = 0u;
                }
        }
    }
}

// =====================================================================
// Kernel 3: tensor-core window attention — 4 heads/CTA, grid (2048, 2).
//   QK^T: bf16 3-product (amplified path).  PV: fp16 2-product —
//   V stored fp16 hi-only; P split fp16 hi + (res x512) lo (f16 accum,
//   /512 at epilogue).  smem/CTA 72 KB.
// =====================================================================
#define AHEAD 17920
#define AQH 0
#define AQL 3584
#define AKH 7168
#define AKL 10752
#define AVH 14336
#define ATTN_SMEM (4 * AHEAD + 512)

__global__ __launch_bounds__(256, 2)
void attn_tc(const float* __restrict__ qkv,
             const float* __restrict__ bias,
             const float* __restrict__ scale,
             __half* __restrict__ attn_out)
{
    extern __shared__ char smem[];
    const uint32_t sb = s2u(smem);
    const int b    = blockIdx.x;
    const int hg   = blockIdx.y;
    const int tid  = threadIdx.x;
    const int lane = tid & 31;
    const int wrp  = tid >> 5;

    // zero V pad rows 49..55 (hi only, 4 slots) + 512B tail
    {
        int i = tid;
        if (i < 112) {
            const int slot = i / 28, rem = i % 28;
            const int rr = 49 + rem / 4, c16 = (rem & 3) * 16;
            *(uint4*)(smem + slot * AHEAD + AVH + rr * 64 + c16) = make_uint4(0, 0, 0, 0);
        } else if (i < 144) {
            *(uint4*)(smem + 4 * AHEAD + (i - 112) * 16) = make_uint4(0, 0, 0, 0);
        }
    }

    // loader: 4-thread teams, each thread owns 8 dims; uniform round count.
    {
        const float* wb = qkv + (size_t)b * NTOK * QKVCOL;
        const int team = tid >> 2, l4 = tid & 3;
#pragma unroll
        for (int it0 = 0; it0 < 256; it0 += 64) {
            const int it  = it0 + team;
            const bool act = (it < 196);
            const int tok  = act ? (it >> 2) : 0;
            const int slot = it & 3;
            const int hh   = hg * 4 + (act ? slot : 0);
            const float* rowp = wb + (size_t)tok * QKVCOL + hh * HD + l4 * 8;

            float4 q0, q1, k0, k1, v0, v1;
            if (act) {
                q0 = *(const float4*)(rowp);
                q1 = *(const float4*)(rowp + 4);
                k0 = *(const float4*)(rowp + 256);
                k1 = *(const float4*)(rowp + 260);
                v0 = *(const float4*)(rowp + 512);
                v1 = *(const float4*)(rowp + 516);
            } else {
                q0 = q1 = k0 = k1 = v0 = v1 = make_float4(0.f, 0.f, 0.f, 0.f);
            }

            float qss = q0.x*q0.x + q0.y*q0.y + q0.z*q0.z + q0.w*q0.w
                      + q1.x*q1.x + q1.y*q1.y + q1.z*q1.z + q1.w*q1.w;
            float kss = k0.x*k0.x + k0.y*k0.y + k0.z*k0.z + k0.w*k0.w
                      + k1.x*k1.x + k1.y*k1.y + k1.z*k1.z + k1.w*k1.w;
#pragma unroll
            for (int o = 1; o < 4; o <<= 1) {
                qss += __shfl_xor_sync(0xffffffffu, qss, o);
                kss += __shfl_xor_sync(0xffffffffu, kss, o);
            }
            if (act) {
                const float qr = rsqrtf(qss) * __ldg(scale + hh);
                const float kr = rsqrtf(kss);
                q0.x *= qr; q0.y *= qr; q0.z *= qr; q0.w *= qr;
                q1.x *= qr; q1.y *= qr; q1.z *= qr; q1.w *= qr;
                k0.x *= kr; k0.y *= kr; k0.z *= kr; k0.w *= kr;
                k1.x *= kr; k1.y *= kr; k1.z *= kr; k1.w *= kr;

                const uint32_t base = (uint32_t)slot * AHEAD + (uint32_t)tok * 64u
                                    + (uint32_t)((l4 ^ ((tok >> 1) & 3)) << 4);
                {
                    float h0 = rbf(q0.x), h1 = rbf(q0.y), h2 = rbf(q0.z), h3 = rbf(q0.w);
                    float h4 = rbf(q1.x), h5 = rbf(q1.y), h6 = rbf(q1.z), h7 = rbf(q1.w);
                    uint4 hu = make_uint4(pk2(h0,h1), pk2(h2,h3), pk2(h4,h5), pk2(h6,h7));
                    uint4 lu = make_uint4(pk2(q0.x-h0,q0.y-h1), pk2(q0.z-h2,q0.w-h3),
                                          pk2(q1.x-h4,q1.y-h5), pk2(q1.z-h6,q1.w-h7));
                    *(uint4*)(smem + AQH + base) = hu;
                    *(uint4*)(smem + AQL + base) = lu;
                }
                {
                    float h0 = rbf(k0.x), h1 = rbf(k0.y), h2 = rbf(k0.z), h3 = rbf(k0.w);
                    float h4 = rbf(k1.x), h5 = rbf(k1.y), h6 = rbf(k1.z), h7 = rbf(k1.w);
                    uint4 hu = make_uint4(pk2(h0,h1), pk2(h2,h3), pk2(h4,h5), pk2(h6,h7));
                    uint4 lu = make_uint4(pk2(k0.x-h0,k0.y-h1), pk2(k0.z-h2,k0.w-h3),
                                          pk2(k1.x-h4,k1.y-h5), pk2(k1.z-h6,k1.w-h7));
                    *(uint4*)(smem + AKH + base) = hu;
                    *(uint4*)(smem + AKL + base) = lu;
                }
                {
                    // V: fp16 hi only
                    uint4 hu = make_uint4(pk2h(v0.x,v0.y), pk2h(v0.z,v0.w),
                                          pk2h(v1.x,v1.y), pk2h(v1.z,v1.w));
                    *(uint4*)(smem + AVH + base) = hu;
                }
            }
        }
    }
    __syncthreads();

    const int slot = wrp >> 1;
    const int h    = hg * 4 + slot;
    const int m0base = (wrp & 1) * 32;
    const uint32_t hb = sb + (uint32_t)slot * AHEAD;
    const float* bslab = bias + h * 3584;
    __half* obase = attn_out + (size_t)b * NTOK * DIMF + h * HD;
    const int qrow = lane >> 2;
    const int qc   = (lane & 3) * 2;

#pragma unroll
    for (int mc = 0; mc < 2; mc++) {
        const int m0 = m0base + mc * 16;
        const int r0 = m0 + qrow;

        // init S with bias (pads read 0); loads hide under QK MMAs
        float S[7][4];
#pragma unroll
        for (int nf = 0; nf < 7; nf++) {
            const int c0 = nf * 8 + qc;
            const float2 b0 = *(const float2*)(bslab + r0 * 56 + c0);
            const float2 b1 = *(const float2*)(bslab + (r0 + 8) * 56 + c0);
            S[nf][0] = b0.x; S[nf][1] = b0.y;
            S[nf][2] = b1.x; S[nf][3] = b1.y;
        }

#pragma unroll
        for (int ks = 0; ks < 2; ks++) {
            uint32_t ah[4], al[4];
            {
                const uint32_t r = (uint32_t)(m0 + ((lane >> 3) & 1) * 8 + (lane & 7));
                const uint32_t cb = (uint32_t)(ks * 32 + (lane >> 4) * 16);
                const uint32_t ad = hb + AQH + r * 64u + swz64(cb, r);
                LDSM_X4(ah, ad);
                LDSM_X4(al, ad + (AQL - AQH));
            }
#pragma unroll
            for (int ng = 0; ng < 4; ng++) {
                uint32_t bh[4], bl[4];
                const uint32_t r = (uint32_t)(ng * 16 + (lane & 7) + ((lane >> 4) << 3));
                const uint32_t cb = (uint32_t)(ks * 32 + ((lane >> 3) & 1) * 16);
                const uint32_t ad = hb + AKH + r * 64u + swz64(cb, r);
                LDSM_X4(bh, ad);
                LDSM_X4(bl, ad + (AKL - AKH));
                MMA_BF(S[2 * ng], ah, bh);
                MMA_BF(S[2 * ng], ah, bl);
                MMA_BF(S[2 * ng], al, bh);
                if (ng < 3) {
                    MMA_BF(S[2 * ng + 1], ah, bh + 2);
                    MMA_BF(S[2 * ng + 1], ah, bl + 2);
                    MMA_BF(S[2 * ng + 1], al, bh + 2);
                }
            }
        }

        // mask + softmax
        {
            float mx0 = -1e30f, mx1 = -1e30f;
#pragma unroll
            for (int nf = 0; nf < 7; nf++) {
                const int c0 = nf * 8 + qc;
                S[nf][0] = (c0     < 49) ? S[nf][0] : -1e30f;
                S[nf][1] = (c0 + 1 < 49) ? S[nf][1] : -1e30f;
                S[nf][2] = (c0     < 49) ? S[nf][2] : -1e30f;
                S[nf][3] = (c0 + 1 < 49) ? S[nf][3] : -1e30f;
                mx0 = fmaxf(mx0, fmaxf(S[nf][0], S[nf][1]));
                mx1 = fmaxf(mx1, fmaxf(S[nf][2], S[nf][3]));
            }
#pragma unroll
            for (int o = 1; o < 4; o <<= 1) {
                mx0 = fmaxf(mx0, __shfl_xor_sync(0xffffffffu, mx0, o));
                mx1 = fmaxf(mx1, __shfl_xor_sync(0xffffffffu, mx1, o));
            }
            float rs0 = 0.0f, rs1 = 0.0f;
#pragma unroll
            for (int nf = 0; nf < 7; nf++) {
                float p0 = __expf(S[nf][0] - mx0);
                float p1 = __expf(S[nf][1] - mx0);
                float p2 = __expf(S[nf][2] - mx1);
                float p3 = __expf(S[nf][3] - mx1);
                S[nf][0] = p0; S[nf][1] = p1; S[nf][2] = p2; S[nf][3] = p3;
                rs0 += p0 + p1;  rs1 += p2 + p3;
            }
#pragma unroll
            for (int o = 1; o < 4; o <<= 1) {
                rs0 += __shfl_xor_sync(0xffffffffu, rs0, o);
                rs1 += __shfl_xor_sync(0xffffffffu, rs1, o);
            }
            const float iv0 = 1.0f / rs0, iv1 = 1.0f / rs1;
#pragma unroll
            for (int nf = 0; nf < 7; nf++) {
                S[nf][0] *= iv0; S[nf][1] *= iv0;
                S[nf][2] *= iv1; S[nf][3] *= iv1;
            }
        }

        // O = P V : fp16 2-product (P hi + P lo x512, V fp16)
        float O[4][4];
        uint32_t Olo[4][2];
#pragma unroll
        for (int n = 0; n < 4; n++) {
#pragma unroll
            for (int q = 0; q < 4; q++) O[n][q] = 0.0f;
            Olo[n][0] = 0u; Olo[n][1] = 0u;
        }

#pragma unroll
        for (int kt = 0; kt < 4; kt++) {
            uint32_t ph[4], pl[4];
            {
                float pa0 = S[2*kt][0], pa1 = S[2*kt][1], pa2 = S[2*kt][2], pa3 = S[2*kt][3];
                float pb0 = 0.f, pb1 = 0.f, pb2 = 0.f, pb3 = 0.f;
                if (kt < 3) {
                    pb0 = S[2*kt+1][0]; pb1 = S[2*kt+1][1];
                    pb2 = S[2*kt+1][2]; pb3 = S[2*kt+1][3];
                }
                const float ha0 = rhf(pa0), ha1 = rhf(pa1), ha2 = rhf(pa2), ha3 = rhf(pa3);
                const float hb0 = rhf(pb0), hb1 = rhf(pb1), hb2 = rhf(pb2), hb3 = rhf(pb3);
                ph[0] = pk2h(ha0, ha1);  ph[1] = pk2h(ha2, ha3);
                ph[2] = pk2h(hb0, hb1);  ph[3] = pk2h(hb2, hb3);
                pl[0] = pk2h((pa0 - ha0) * PSC, (pa1 - ha1) * PSC);
                pl[1] = pk2h((pa2 - ha2) * PSC, (pa3 - ha3) * PSC);
                pl[2] = pk2h((pb0 - hb0) * PSC, (pb1 - hb1) * PSC);
                pl[3] = pk2h((pb2 - hb2) * PSC, (pb3 - hb3) * PSC);
            }
#pragma unroll
            for (int vg = 0; vg < 2; vg++) {
                uint32_t vh[4];
                const uint32_t kr = (uint32_t)(kt * 16 + ((lane >> 3) & 1) * 8 + (lane & 7));
                const uint32_t cb = (uint32_t)(vg * 32 + (lane >> 4) * 16);
                LDSM_X4T(vh, hb + AVH + kr * 64u + swz64(cb, kr));
#pragma unroll
                for (int nn = 0; nn < 2; nn++) {
                    MMA_FH(O[vg * 2 + nn], ph, vh + nn * 2);
                    MMA_HH(Olo[vg * 2 + nn], pl, vh + nn * 2);
                }
            }
        }

        // store rows < 49 as fp16 (lo term rescaled /512)
        {
#pragma unroll
            for (int nf = 0; nf < 4; nf++) {
                const int c = nf * 8 + qc;
                float2 c01 = __half22float2(*(const __half2*)&Olo[nf][0]);
                float2 c23 = __half22float2(*(const __half2*)&Olo[nf][1]);
                if (r0 < NTOK)
                    *(uint32_t*)(obase + (size_t)r0 * DIMF + c) =
                        pk2h(O[nf][0] + c01.x * PSCINV, O[nf][1] + c01.y * PSCINV);
                if (r0 + 8 < NTOK)
                    *(uint32_t*)(obase + (size_t)(r0 + 8) * DIMF + c) =
                        pk2h(O[nf][2] + c23.x * PSCINV, O[nf][3] + c23.y * PSCINV);
            }
        }
    }
}

// =====================================================================
// launch
// =====================================================================
extern "C" void kernel_launch(void* const* d_in, const int* in_sizes, int n_in,
                              void* d_out, int out_size)
{
    const float* x           = (const float*)d_in[0];
    const float* qkv_w       = (const float*)d_in[1];
    const float* qkv_b       = (const float*)d_in[2];
    const float* proj_w      = (const float*)d_in[3];
    const float* proj_b      = (const float*)d_in[4];
    const float* logit_scale = (const float*)d_in[5];
    const float* cpb_w1      = (const float*)d_in[6];
    const float* cpb_b1      = (const float*)d_in[7];
    const float* cpb_w2      = (const float*)d_in[8];
    float* out = (float*)d_out;

    float *qkvbuf, *attnbuf, *biasbuf, *scalebuf;
    unsigned char *wqbuf, *wpbuf;
    cudaGetSymbolAddress((void**)&qkvbuf,   g_qkv);
    cudaGetSymbolAddress((void**)&attnbuf,  g_attn);
    cudaGetSymbolAddress((void**)&biasbuf,  g_bias);
    cudaGetSymbolAddress((void**)&scalebuf, g_scale);
    cudaGetSymbolAddress((void**)&wqbuf,    g_wq);
    cudaGetSymbolAddress((void**)&wpbuf,    g_wp);

    cudaFuncSetAttribute((const void*)gemm_mma<false, 2>,
                         cudaFuncAttributeMaxDynamicSharedMemorySize, GEMM_SMEM);
    cudaFuncSetAttribute((const void*)gemm_mma<true, 1>,
                         cudaFuncAttributeMaxDynamicSharedMemorySize, GEMM_SMEM);
    cudaFuncSetAttribute((const void*)attn_tc,
                         cudaFuncAttributeMaxDynamicSharedMemorySize, ATTN_SMEM);

    cpb_kernel<<<1, 256>>>(logit_scale, cpb_w1, cpb_b1, cpb_w2, biasbuf, scalebuf);
    wsplit_kernel<<<128, 256>>>(qkv_w, proj_w, wqbuf, wpbuf);

    gemm_mma<false, 2><<<MROWS / 64, 256, GEMM_SMEM>>>(x, wqbuf, qkv_b, qkvbuf, 6);

    attn_tc<<<dim3(B_WIN, 2), 256, ATTN_SMEM>>>(qkvbuf, biasbuf, scalebuf,
                                                (__half*)attnbuf);

    gemm_mma<true, 1><<<MROWS / 64, 256, GEMM_SMEM>>>(attnbuf, wpbuf, proj_b, out, 2);
}

// round 15
// speedup vs baseline: 1.0454x; 1.0454x over previous
#include <cuda_runtime.h>
#include <cuda_bf16.h>
#include <cuda_fp16.h>
#include <cstdint>

// ---------------- problem constants ----------------
#define B_WIN  2048
#define NTOK   49
#define DIMF   256
#define HEADS  8
#define HD     32
#define MROWS  (B_WIN * NTOK)        // 100352
#define QKVCOL 768

#define LOSC   2048.0f               // GEMM lo-term pre-scale
#define LOINV  4.8828125e-4f         // 1/2048
#define PSC    512.0f                // attn P-lo pre-scale
#define PSCINV 1.953125e-3f          // 1/512

// ---------------- scratch ----------------
__device__ float g_qkv [MROWS * QKVCOL];
__device__ float g_attn[MROWS * DIMF];      // used as __half buffer (half of it)
__device__ float g_bias[HEADS * 64 * 56];   // padded [8][64][56]; pads stay 0
__device__ float g_scale[HEADS];
__device__ unsigned char g_wq[48 * 16384];  // fp16 hi/lo chunks
__device__ unsigned char g_wp[16 * 16384];

// ---------------- helpers ----------------
static __device__ __forceinline__ uint32_t s2u(const void* p) {
    uint32_t a;
    asm("{ .reg .u64 t; cvta.to.shared.u64 t, %1; cvt.u32.u64 %0, t; }" : "=r"(a) : "l"(p));
    return a;
}
static __device__ __forceinline__ uint32_t swz(uint32_t byte_in_row, uint32_t row) {
    return (byte_in_row & ~0x7Fu) | ((byte_in_row & 0x7Fu) ^ ((row & 7u) << 4));
}
static __device__ __forceinline__ uint32_t swz64(uint32_t c, uint32_t row) {
    return (c & 0xFu) | (((((c >> 4) ^ ((row >> 1) & 3u))) & 3u) << 4);
}

#define LDSM_X4(r, a)                                                        \
    asm volatile("ldmatrix.sync.aligned.m8n8.x4.shared.b16 {%0,%1,%2,%3}, [%4];" \
        : "=r"((r)[0]), "=r"((r)[1]), "=r"((r)[2]), "=r"((r)[3]) : "r"(a))
#define LDSM_X4T(r, a)                                                       \
    asm volatile("ldmatrix.sync.aligned.m8n8.x4.trans.shared.b16 {%0,%1,%2,%3}, [%4];" \
        : "=r"((r)[0]), "=r"((r)[1]), "=r"((r)[2]), "=r"((r)[3]) : "r"(a))

#define MMA_BF(c, a, b)                                                      \
    asm volatile("mma.sync.aligned.m16n8k16.row.col.f32.bf16.bf16.f32 "      \
        "{%0,%1,%2,%3}, {%4,%5,%6,%7}, {%8,%9}, {%0,%1,%2,%3};"              \
        : "+f"((c)[0]), "+f"((c)[1]), "+f"((c)[2]), "+f"((c)[3])             \
        : "r"((a)[0]), "r"((a)[1]), "r"((a)[2]), "r"((a)[3]),                \
          "r"((b)[0]), "r"((b)[1]))
#define MMA_FH(c, a, b)                                                      \
    asm volatile("mma.sync.aligned.m16n8k16.row.col.f32.f16.f16.f32 "        \
        "{%0,%1,%2,%3}, {%4,%5,%6,%7}, {%8,%9}, {%0,%1,%2,%3};"              \
        : "+f"((c)[0]), "+f"((c)[1]), "+f"((c)[2]), "+f"((c)[3])             \
        : "r"((a)[0]), "r"((a)[1]), "r"((a)[2]), "r"((a)[3]),                \
          "r"((b)[0]), "r"((b)[1]))
#define MMA_HH(c2, a, b)                                                     \
    asm volatile("mma.sync.aligned.m16n8k16.row.col.f16.f16.f16.f16 "        \
        "{%0,%1}, {%2,%3,%4,%5}, {%6,%7}, {%0,%1};"                          \
        : "+r"((c2)[0]), "+r"((c2)[1])                                       \
        : "r"((a)[0]), "r"((a)[1]), "r"((a)[2]), "r"((a)[3]),                \
          "r"((b)[0]), "r"((b)[1]))

#define CP16(d, s) \
    asm volatile("cp.async.cg.shared.global [%0], [%1], 16;" :: "r"(d), "l"(s) : "memory")
#define CP_COMMIT() asm volatile("cp.async.commit_group;" ::: "memory")
#define CP_WAIT(n)  asm volatile("cp.async.wait_group %0;" :: "n"(n) : "memory")

static __device__ __forceinline__ uint32_t pk2(float x, float y) {   // bf16x2
    uint32_t r;
    asm("cvt.rn.bf16x2.f32 %0, %1, %2;" : "=r"(r) : "f"(y), "f"(x));
    return r;
}
static __device__ __forceinline__ uint32_t pk2h(float x, float y) {  // f16x2
    uint32_t r;
    asm("cvt.rn.f16x2.f32 %0, %1, %2;" : "=r"(r) : "f"(y), "f"(x));
    return r;
}
static __device__ __forceinline__ float rbf(float x) {
    return __bfloat162float(__float2bfloat16_rn(x));
}
static __device__ __forceinline__ float rhf(float x) {
    return __half2float(__float2half_rn(x));
}

// =====================================================================
// Kernel 1: CPB-MLP bias table + logit scale
// =====================================================================
__device__ __forceinline__ float cpb_coord(int i) {
    float x = (float)(i - 6) * (8.0f / 6.0f);
    return copysignf(log1pf(fabsf(x)) * 0.4808983469629878f, x);
}

__global__ void cpb_kernel(const float* __restrict__ logit_scale,
                           const float* __restrict__ w1,
                           const float* __restrict__ b1,
                           const float* __restrict__ w2,
                           float* __restrict__ bias_out,
                           float* __restrict__ scale_out)
{
    __shared__ float table[169][HEADS];
    const int tid = threadIdx.x;

    if (tid < HEADS) {
        float ls = logit_scale[tid];
        ls = fminf(ls, logf(100.0f));
        ls = fmaxf(ls, -100.0f);
        scale_out[tid] = expf(ls);
    }
    for (int e = tid; e < 169; e += blockDim.x) {
        const int i = e / 13, j = e % 13;
        const float c0 = cpb_coord(i);
        const float c1 = cpb_coord(j);
        float acc[HEADS];
#pragma unroll
        for (int hh = 0; hh < HEADS; hh++) acc[hh] = 0.0f;
        for (int kk = 0; kk < 512; kk++) {
            float hpre = c0 * w1[kk] + c1 * w1[512 + kk] + b1[kk];
            float g = 0.5f * hpre * (1.0f + erff(hpre * 0.7071067811865475f));
#pragma unroll
            for (int hh = 0; hh < HEADS; hh++) acc[hh] += g * w2[kk * 8 + hh];
        }
#pragma unroll
        for (int hh = 0; hh < HEADS; hh++) table[e][hh] = acc[hh];
    }
    __syncthreads();

    for (int idx = tid; idx < HEADS * NTOK * NTOK; idx += blockDim.x) {
        const int hh  = idx / (NTOK * NTOK);
        const int rem = idx % (NTOK * NTOK);
        const int r   = rem / NTOK;
        const int c   = rem % NTOK;
        const int dh  = (r / 7) - (c / 7) + 6;
        const int dw  = (r % 7) - (c % 7) + 6;
        const float v = table[dh * 13 + dw][hh];
        bias_out[hh * 3584 + r * 56 + c] = 16.0f / (1.0f + __expf(-v));
    }
}

// =====================================================================
// Kernel 1b: split weights fp32 -> hi/lo fp16 chunks (lo pre-scaled x2048)
// =====================================================================
__global__ void wsplit_kernel(const float* __restrict__ wq, const float* __restrict__ wp,
                              unsigned char* __restrict__ oq, unsigned char* __restrict__ op)
{
    const int stride = gridDim.x * blockDim.x;
    const int t0 = blockIdx.x * blockDim.x + threadIdx.x;
    for (int idx = t0; idx < 256 * QKVCOL; idx += stride) {
        const int k = idx / QKVCOL, n = idx % QKVCOL;
        float f = wq[idx];
        __half h = __float2half_rn(f);
        __half l = __float2half_rn((f - __half2float(h)) * LOSC);
        const uint32_t off = (uint32_t)((n >> 7) * 8 + (k >> 5)) * 16384u
                           + (uint32_t)(k & 31) * 256u + swz((uint32_t)(n & 127) * 2u, (uint32_t)k);
        *(__half*)(oq + off)        = h;
        *(__half*)(oq + off + 8192) = l;
    }
    for (int idx = t0; idx < 256 * 256; idx += stride) {
        const int k = idx >> 8, n = idx & 255;
        float f = wp[idx];
        __half h = __float2half_rn(f);
        __half l = __float2half_rn((f - __half2float(h)) * LOSC);
        const uint32_t off = (uint32_t)((n >> 7) * 8 + (k >> 5)) * 16384u
                           + (uint32_t)(k & 31) * 256u + swz((uint32_t)(n & 127) * 2u, (uint32_t)k);
        *(__half*)(op + off)        = h;
        *(__half*)(op + off + 8192) = l;
    }
}

// =====================================================================
// Kernel 2: fp16 GEMM — 32KB superchunks (2 k-chunks per sync),
//   2-stage double buffer, prefetch distance 1.
//   NPROD=2: A*Whi (f32) + A*Wlo' (f16); NPROD=1: hi only (8KB/chunk).
//   smem: A 32KB + 2 stages (2*CHSLOT*2) = 96KB (NPROD=2) / 64KB (1).
// =====================================================================
#define SMW_OFF 32768

template<bool AHALF, int NPROD>
__global__ __launch_bounds__(256, 2)
void gemm_mma(const void* __restrict__ Ain, const unsigned char* __restrict__ Wp,
              const float* __restrict__ bias, float* __restrict__ C, int NT)
{
    extern __shared__ char smem[];
    const uint32_t sb = s2u(smem);
    const int tid  = threadIdx.x;
    const int lane = tid & 31;
    const int w    = tid >> 5;
    const int row0 = blockIdx.x * 64;
    const int Ncols = NT * 128;
    constexpr int NCP    = (NPROD == 2) ? 4 : 2;         // 4KB segments per chunk
    constexpr uint32_t CHSLOT = NCP * 4096u;             // chunk slot in stage
    constexpr uint32_t SCB    = 2u * CHSLOT;             // superchunk stage bytes

    // A into swizzled smem (64 rows x 512B)
    if (AHALF) {
        const __half* A16 = (const __half*)Ain;
        for (int i = tid; i < 2048; i += 256) {
            const int r  = i >> 5;
            const int c8 = (i & 31) << 3;
            uint4 v = *(const uint4*)(A16 + (size_t)(row0 + r) * 256 + c8);
            const uint32_t off = (uint32_t)r * 512u + swz((uint32_t)c8 * 2u, (uint32_t)r);
            *(uint4*)(smem + off) = v;
        }
    } else {
        const float* A = (const float*)Ain;
        for (int i = tid; i < 4096; i += 256) {
            const int r  = i >> 6;
            const int c4 = (i & 63) << 2;
            float4 a = *(const float4*)(A + (size_t)(row0 + r) * 256 + c4);
            const uint32_t off = (uint32_t)r * 512u + swz((uint32_t)c4 * 2u, (uint32_t)r);
            uint2 hu; hu.x = pk2h(a.x, a.y); hu.y = pk2h(a.z, a.w);
            *(uint2*)(smem + off) = hu;
        }
    }

    const int wm = w & 1;
    const int wn = w >> 1;
    const int NSC = NT * 4;       // superchunks (2 k-chunks each)

    // prefetch superchunk 0 into stage 0
    {
#pragma unroll
        for (int c2 = 0; c2 < 2; c2++) {
            const unsigned char* src = Wp + (size_t)c2 * 16384;
            const uint32_t dst = sb + SMW_OFF + (uint32_t)c2 * CHSLOT;
#pragma unroll
            for (int j = 0; j < NCP; j++)
                CP16(dst + (uint32_t)(tid * 16 + j * 4096), src + tid * 16 + j * 4096);
        }
        CP_COMMIT();
    }

    float    acc [2][4][4];
    uint32_t acch[2][4][2];
    int nt = 0;
#pragma unroll
    for (int mf = 0; mf < 2; mf++)
#pragma unroll
        for (int nf = 0; nf < 4; nf++) {
#pragma unroll
            for (int q = 0; q < 4; q++) acc[mf][nf][q] = 0.0f;
            acch[mf][nf][0] = 0u; acch[mf][nf][1] = 0u;
        }

    for (int s = 0; s < NSC; s++) {
        CP_WAIT(0);          // superchunk s landed
        __syncthreads();     // all warps done with s-1 (frees stage (s+1)&1)

        if (s + 1 < NSC) {
            const uint32_t stg = sb + SMW_OFF + (uint32_t)((s + 1) & 1) * SCB;
#pragma unroll
            for (int c2 = 0; c2 < 2; c2++) {
                const unsigned char* src = Wp + (size_t)(2 * (s + 1) + c2) * 16384;
                const uint32_t dst = stg + (uint32_t)c2 * CHSLOT;
#pragma unroll
                for (int j = 0; j < NCP; j++)
                    CP16(dst + (uint32_t)(tid * 16 + j * 4096), src + tid * 16 + j * 4096);
            }
        }
        CP_COMMIT();

        const uint32_t st0 = sb + SMW_OFF + (uint32_t)(s & 1) * SCB;

#pragma unroll
        for (int c2 = 0; c2 < 2; c2++) {
            const uint32_t st = st0 + (uint32_t)c2 * CHSLOT;
            const int kc = ((s & 3) << 1) | c2;

#pragma unroll
            for (int ks = 0; ks < 2; ks++) {
                uint32_t ah[2][4];
                const int arow = wm * 32 + ((lane >> 3) & 1) * 8 + (lane & 7);
                const int kg   = kc * 32 + ks * 16 + ((lane >> 4) << 3);
#pragma unroll
                for (int mf = 0; mf < 2; mf++) {
                    const uint32_t r = (uint32_t)(arow + mf * 16);
                    LDSM_X4(ah[mf], sb + r * 512u + swz((uint32_t)kg * 2u, r));
                }
                uint32_t bh[2][4], bl[2][4];
                const uint32_t krow = (uint32_t)(ks * 16 + ((lane >> 3) & 1) * 8 + (lane & 7));
#pragma unroll
                for (int nf2 = 0; nf2 < 2; nf2++) {
                    const uint32_t ncol = (uint32_t)(wn * 32 + nf2 * 16 + (lane >> 4) * 8);
                    const uint32_t addr = st + krow * 256u + swz(ncol * 2u, krow);
                    LDSM_X4T(bh[nf2], addr);
                    if (NPROD == 2) LDSM_X4T(bl[nf2], addr + 8192u);
                }
#pragma unroll
                for (int mf = 0; mf < 2; mf++)
#pragma unroll
                    for (int nf = 0; nf < 4; nf++) {
                        uint32_t* bph = &bh[nf >> 1][(nf & 1) * 2];
                        MMA_FH(acc[mf][nf], ah[mf], bph);
                        if (NPROD == 2) {
                            uint32_t* bpl = &bl[nf >> 1][(nf & 1) * 2];
                            MMA_HH(acch[mf][nf], ah[mf], bpl);
                        }
                    }
            }
        }

        if ((s & 3) == 3) {
            const int g = lane >> 2, t = lane & 3;
#pragma unroll
            for (int nf = 0; nf < 4; nf++) {
                const int col = nt * 128 + wn * 32 + nf * 8 + t * 2;
                const float2 bv = *(const float2*)(bias + col);
#pragma unroll
                for (int mf = 0; mf < 2; mf++) {
                    const int row = row0 + wm * 32 + mf * 16 + g;
                    float lo0 = 0.f, lo1 = 0.f, lo2 = 0.f, lo3 = 0.f;
                    if (NPROD == 2) {
                        float2 c01 = __half22float2(*(const __half2*)&acch[mf][nf][0]);
                        float2 c23 = __half22float2(*(const __half2*)&acch[mf][nf][1]);
                        lo0 = c01.x * LOINV; lo1 = c01.y * LOINV;
                        lo2 = c23.x * LOINV; lo3 = c23.y * LOINV;
                    }
                    float2 v0 = make_float2(acc[mf][nf][0] + lo0 + bv.x,
                                            acc[mf][nf][1] + lo1 + bv.y);
                    float2 v1 = make_float2(acc[mf][nf][2] + lo2 + bv.x,
                                            acc[mf][nf][3] + lo3 + bv.y);
                    *(float2*)(C + (size_t)row * Ncols + col)       = v0;
                    *(float2*)(C + (size_t)(row + 8) * Ncols + col) = v1;
                }
            }
            nt++;
#pragma unroll
            for (int mf = 0; mf < 2; mf++)
#pragma unroll
                for (int nf = 0; nf < 4; nf++) {
#pragma unroll
                    for (int q = 0; q < 4; q++) acc[mf][nf][q] = 0.0f;
                    acch[mf][nf][0] = 0u; acch[mf][nf][1] = 0u;
                }
        }
    }
}

// =====================================================================
// Kernel 3: tensor-core window attention (unchanged from R14)
//   QK^T bf16 3-product; PV fp16 2-product (V hi-only); fp16 output.
// =====================================================================
#define AHEAD 17920
#define AQH 0
#define AQL 3584
#define AKH 7168
#define AKL 10752
#define AVH 14336
#define ATTN_SMEM (4 * AHEAD + 512)

__global__ __launch_bounds__(256, 2)
void attn_tc(const float* __restrict__ qkv,
             const float* __restrict__ bias,
             const float* __restrict__ scale,
             __half* __restrict__ attn_out)
{
    extern __shared__ char smem[];
    const uint32_t sb = s2u(smem);
    const int b    = blockIdx.x;
    const int hg   = blockIdx.y;
    const int tid  = threadIdx.x;
    const int lane = tid & 31;
    const int wrp  = tid >> 5;

    {
        int i = tid;
        if (i < 112) {
            const int slot = i / 28, rem = i % 28;
            const int rr = 49 + rem / 4, c16 = (rem & 3) * 16;
            *(uint4*)(smem + slot * AHEAD + AVH + rr * 64 + c16) = make_uint4(0, 0, 0, 0);
        } else if (i < 144) {
            *(uint4*)(smem + 4 * AHEAD + (i - 112) * 16) = make_uint4(0, 0, 0, 0);
        }
    }

    {
        const float* wb = qkv + (size_t)b * NTOK * QKVCOL;
        const int team = tid >> 2, l4 = tid & 3;
#pragma unroll
        for (int it0 = 0; it0 < 256; it0 += 64) {
            const int it  = it0 + team;
            const bool act = (it < 196);
            const int tok  = act ? (it >> 2) : 0;
            const int slot = it & 3;
            const int hh   = hg * 4 + (act ? slot : 0);
            const float* rowp = wb + (size_t)tok * QKVCOL + hh * HD + l4 * 8;

            float4 q0, q1, k0, k1, v0, v1;
            if (act) {
                q0 = *(const float4*)(rowp);
                q1 = *(const float4*)(rowp + 4);
                k0 = *(const float4*)(rowp + 256);
                k1 = *(const float4*)(rowp + 260);
                v0 = *(const float4*)(rowp + 512);
                v1 = *(const float4*)(rowp + 516);
            } else {
                q0 = q1 = k0 = k1 = v0 = v1 = make_float4(0.f, 0.f, 0.f, 0.f);
            }

            float qss = q0.x*q0.x + q0.y*q0.y + q0.z*q0.z + q0.w*q0.w
                      + q1.x*q1.x + q1.y*q1.y + q1.z*q1.z + q1.w*q1.w;
            float kss = k0.x*k0.x + k0.y*k0.y + k0.z*k0.z + k0.w*k0.w
                      + k1.x*k1.x + k1.y*k1.y + k1.z*k1.z + k1.w*k1.w;
#pragma unroll
            for (int o = 1; o < 4; o <<= 1) {
                qss += __shfl_xor_sync(0xffffffffu, qss, o);
                kss += __shfl_xor_sync(0xffffffffu, kss, o);
            }
            if (act) {
                const float qr = rsqrtf(qss) * __ldg(scale + hh);
                const float kr = rsqrtf(kss);
                q0.x *= qr; q0.y *= qr; q0.z *= qr; q0.w *= qr;
                q1.x *= qr; q1.y *= qr; q1.z *= qr; q1.w *= qr;
                k0.x *= kr; k0.y *= kr; k0.z *= kr; k0.w *= kr;
                k1.x *= kr; k1.y *= kr; k1.z *= kr; k1.w *= kr;

                const uint32_t base = (uint32_t)slot * AHEAD + (uint32_t)tok * 64u
                                    + (uint32_t)((l4 ^ ((tok >> 1) & 3)) << 4);
                {
                    float h0 = rbf(q0.x), h1 = rbf(q0.y), h2 = rbf(q0.z), h3 = rbf(q0.w);
                    float h4 = rbf(q1.x), h5 = rbf(q1.y), h6 = rbf(q1.z), h7 = rbf(q1.w);
                    uint4 hu = make_uint4(pk2(h0,h1), pk2(h2,h3), pk2(h4,h5), pk2(h6,h7));
                    uint4 lu = make_uint4(pk2(q0.x-h0,q0.y-h1), pk2(q0.z-h2,q0.w-h3),
                                          pk2(q1.x-h4,q1.y-h5), pk2(q1.z-h6,q1.w-h7));
                    *(uint4*)(smem + AQH + base) = hu;
                    *(uint4*)(smem + AQL + base) = lu;
                }
                {
                    float h0 = rbf(k0.x), h1 = rbf(k0.y), h2 = rbf(k0.z), h3 = rbf(k0.w);
                    float h4 = rbf(k1.x), h5 = rbf(k1.y), h6 = rbf(k1.z), h7 = rbf(k1.w);
                    uint4 hu = make_uint4(pk2(h0,h1), pk2(h2,h3), pk2(h4,h5), pk2(h6,h7));
                    uint4 lu = make_uint4(pk2(k0.x-h0,k0.y-h1), pk2(k0.z-h2,k0.w-h3),
                                          pk2(k1.x-h4,k1.y-h5), pk2(k1.z-h6,k1.w-h7));
                    *(uint4*)(smem + AKH + base) = hu;
                    *(uint4*)(smem + AKL + base) = lu;
                }
                {
                    uint4 hu = make_uint4(pk2h(v0.x,v0.y), pk2h(v0.z,v0.w),
                                          pk2h(v1.x,v1.y), pk2h(v1.z,v1.w));
                    *(uint4*)(smem + AVH + base) = hu;
                }
            }
        }
    }
    __syncthreads();

    const int slot = wrp >> 1;
    const int h    = hg * 4 + slot;
    const int m0base = (wrp & 1) * 32;
    const uint32_t hb = sb + (uint32_t)slot * AHEAD;
    const float* bslab = bias + h * 3584;
    __half* obase = attn_out + (size_t)b * NTOK * DIMF + h * HD;
    const int qrow = lane >> 2;
    const int qc   = (lane & 3) * 2;

#pragma unroll
    for (int mc = 0; mc < 2; mc++) {
        const int m0 = m0base + mc * 16;
        const int r0 = m0 + qrow;

        float S[7][4];
#pragma unroll
        for (int nf = 0; nf < 7; nf++) {
            const int c0 = nf * 8 + qc;
            const float2 b0 = *(const float2*)(bslab + r0 * 56 + c0);
            const float2 b1 = *(const float2*)(bslab + (r0 + 8) * 56 + c0);
            S[nf][0] = b0.x; S[nf][1] = b0.y;
            S[nf][2] = b1.x; S[nf][3] = b1.y;
        }

#pragma unroll
        for (int ks = 0; ks < 2; ks++) {
            uint32_t ah[4], al[4];
            {
                const uint32_t r = (uint32_t)(m0 + ((lane >> 3) & 1) * 8 + (lane & 7));
                const uint32_t cb = (uint32_t)(ks * 32 + (lane >> 4) * 16);
                const uint32_t ad = hb + AQH + r * 64u + swz64(cb, r);
                LDSM_X4(ah, ad);
                LDSM_X4(al, ad + (AQL - AQH));
            }
#pragma unroll
            for (int ng = 0; ng < 4; ng++) {
                uint32_t bh[4], bl[4];
                const uint32_t r = (uint32_t)(ng * 16 + (lane & 7) + ((lane >> 4) << 3));
                const uint32_t cb = (uint32_t)(ks * 32 + ((lane >> 3) & 1) * 16);
                const uint32_t ad = hb + AKH + r * 64u + swz64(cb, r);
                LDSM_X4(bh, ad);
                LDSM_X4(bl, ad + (AKL - AKH));
                MMA_BF(S[2 * ng], ah, bh);
                MMA_BF(S[2 * ng], ah, bl);
                MMA_BF(S[2 * ng], al, bh);
                if (ng < 3) {
                    MMA_BF(S[2 * ng + 1], ah, bh + 2);
                    MMA_BF(S[2 * ng + 1], ah, bl + 2);
                    MMA_BF(S[2 * ng + 1], al, bh + 2);
                }
            }
        }

        {
            float mx0 = -1e30f, mx1 = -1e30f;
#pragma unroll
            for (int nf = 0; nf < 7; nf++) {
                const int c0 = nf * 8 + qc;
                S[nf][0] = (c0     < 49) ? S[nf][0] : -1e30f;
                S[nf][1] = (c0 + 1 < 49) ? S[nf][1] : -1e30f;
                S[nf][2] = (c0     < 49) ? S[nf][2] : -1e30f;
                S[nf][3] = (c0 + 1 < 49) ? S[nf][3] : -1e30f;
                mx0 = fmaxf(mx0, fmaxf(S[nf][0], S[nf][1]));
                mx1 = fmaxf(mx1, fmaxf(S[nf][2], S[nf][3]));
            }
#pragma unroll
            for (int o = 1; o < 4; o <<= 1) {
                mx0 = fmaxf(mx0, __shfl_xor_sync(0xffffffffu, mx0, o));
                mx1 = fmaxf(mx1, __shfl_xor_sync(0xffffffffu, mx1, o));
            }
            float rs0 = 0.0f, rs1 = 0.0f;
#pragma unroll
            for (int nf = 0; nf < 7; nf++) {
                float p0 = __expf(S[nf][0] - mx0);
                float p1 = __expf(S[nf][1] - mx0);
                float p2 = __expf(S[nf][2] - mx1);
                float p3 = __expf(S[nf][3] - mx1);
                S[nf][0] = p0; S[nf][1] = p1; S[nf][2] = p2; S[nf][3] = p3;
                rs0 += p0 + p1;  rs1 += p2 + p3;
            }
#pragma unroll
            for (int o = 1; o < 4; o <<= 1) {
                rs0 += __shfl_xor_sync(0xffffffffu, rs0, o);
                rs1 += __shfl_xor_sync(0xffffffffu, rs1, o);
            }
            const float iv0 = 1.0f / rs0, iv1 = 1.0f / rs1;
#pragma unroll
            for (int nf = 0; nf < 7; nf++) {
                S[nf][0] *= iv0; S[nf][1] *= iv0;
                S[nf][2] *= iv1; S[nf][3] *= iv1;
            }
        }

        float O[4][4];
        uint32_t Olo[4][2];
#pragma unroll
        for (int n = 0; n < 4; n++) {
#pragma unroll
            for (int q = 0; q < 4; q++) O[n][q] = 0.0f;
            Olo[n][0] = 0u; Olo[n][1] = 0u;
        }

#pragma unroll
        for (int kt = 0; kt < 4; kt++) {
            uint32_t ph[4], pl[4];
            {
                float pa0 = S[2*kt][0], pa1 = S[2*kt][1], pa2 = S[2*kt][2], pa3 = S[2*kt][3];
                float pb0 = 0.f, pb1 = 0.f, pb2 = 0.f, pb3 = 0.f;
                if (kt < 3) {
                    pb0 = S[2*kt+1][0]; pb1 = S[2*kt+1][1];
                    pb2 = S[2*kt+1][2]; pb3 = S[2*kt+1][3];
                }
                const float ha0 = rhf(pa0), ha1 = rhf(pa1), ha2 = rhf(pa2), ha3 = rhf(pa3);
                const float hb0 = rhf(pb0), hb1 = rhf(pb1), hb2 = rhf(pb2), hb3 = rhf(pb3);
                ph[0] = pk2h(ha0, ha1);  ph[1] = pk2h(ha2, ha3);
                ph[2] = pk2h(hb0, hb1);  ph[3] = pk2h(hb2, hb3);
                pl[0] = pk2h((pa0 - ha0) * PSC, (pa1 - ha1) * PSC);
                pl[1] = pk2h((pa2 - ha2) * PSC, (pa3 - ha3) * PSC);
                pl[2] = pk2h((pb0 - hb0) * PSC, (pb1 - hb1) * PSC);
                pl[3] = pk2h((pb2 - hb2) * PSC, (pb3 - hb3) * PSC);
            }
#pragma unroll
            for (int vg = 0; vg < 2; vg++) {
                uint32_t vh[4];
                const uint32_t kr = (uint32_t)(kt * 16 + ((lane >> 3) & 1) * 8 + (lane & 7));
                const uint32_t cb = (uint32_t)(vg * 32 + (lane >> 4) * 16);
                LDSM_X4T(vh, hb + AVH + kr * 64u + swz64(cb, kr));
#pragma unroll
                for (int nn = 0; nn < 2; nn++) {
                    MMA_FH(O[vg * 2 + nn], ph, vh + nn * 2);
                    MMA_HH(Olo[vg * 2 + nn], pl, vh + nn * 2);
                }
            }
        }

        {
#pragma unroll
            for (int nf = 0; nf < 4; nf++) {
                const int c = nf * 8 + qc;
                float2 c01 = __half22float2(*(const __half2*)&Olo[nf][0]);
                float2 c23 = __half22float2(*(const __half2*)&Olo[nf][1]);
                if (r0 < NTOK)
                    *(uint32_t*)(obase + (size_t)r0 * DIMF + c) =
                        pk2h(O[nf][0] + c01.x * PSCINV, O[nf][1] + c01.y * PSCINV);
                if (r0 + 8 < NTOK)
                    *(uint32_t*)(obase + (size_t)(r0 + 8) * DIMF + c) =
                        pk2h(O[nf][2] + c23.x * PSCINV, O[nf][3] + c23.y * PSCINV);
            }
        }
    }
}

// =====================================================================
// launch
// =====================================================================
extern "C" void kernel_launch(void* const* d_in, const int* in_sizes, int n_in,
                              void* d_out, int out_size)
{
    const float* x           = (const float*)d_in[0];
    const float* qkv_w       = (const float*)d_in[1];
    const float* qkv_b       = (const float*)d_in[2];
    const float* proj_w      = (const float*)d_in[3];
    const float* proj_b      = (const float*)d_in[4];
    const float* logit_scale = (const float*)d_in[5];
    const float* cpb_w1      = (const float*)d_in[6];
    const float* cpb_b1      = (const float*)d_in[7];
    const float* cpb_w2      = (const float*)d_in[8];
    float* out = (float*)d_out;

    float *qkvbuf, *attnbuf, *biasbuf, *scalebuf;
    unsigned char *wqbuf, *wpbuf;
    cudaGetSymbolAddress((void**)&qkvbuf,   g_qkv);
    cudaGetSymbolAddress((void**)&attnbuf,  g_attn);
    cudaGetSymbolAddress((void**)&biasbuf,  g_bias);
    cudaGetSymbolAddress((void**)&scalebuf, g_scale);
    cudaGetSymbolAddress((void**)&wqbuf,    g_wq);
    cudaGetSymbolAddress((void**)&wpbuf,    g_wp);

    const int SMEM2 = 32768 + 2 * 32768;   // 96KB (NPROD=2)
    const int SMEM1 = 32768 + 2 * 16384;   // 64KB (NPROD=1)

    cudaFuncSetAttribute((const void*)gemm_mma<false, 2>,
                         cudaFuncAttributeMaxDynamicSharedMemorySize, SMEM2);
    cudaFuncSetAttribute((const void*)gemm_mma<true, 1>,
                         cudaFuncAttributeMaxDynamicSharedMemorySize, SMEM1);
    cudaFuncSetAttribute((const void*)attn_tc,
                         cudaFuncAttributeMaxDynamicSharedMemorySize, ATTN_SMEM);

    cpb_kernel<<<1, 256>>>(logit_scale, cpb_w1, cpb_b1, cpb_w2, biasbuf, scalebuf);
    wsplit_kernel<<<128, 256>>>(qkv_w, proj_w, wqbuf, wpbuf);

    gemm_mma<false, 2><<<MROWS / 64, 256, SMEM2>>>(x, wqbuf, qkv_b, qkvbuf, 6);

    attn_tc<<<dim3(B_WIN, 2), 256, ATTN_SMEM>>>(qkvbuf, biasbuf, scalebuf,
                                                (__half*)attnbuf);

    gemm_mma<true, 1><<<MROWS / 64, 256, SMEM1>>>(attnbuf, wpbuf, proj_b, out, 2);
}

// round 16
// speedup vs baseline: 1.2043x; 1.1519x over previous
#include <cuda_runtime.h>
#include <cuda_bf16.h>
#include <cuda_fp16.h>
#include <cstdint>

// ---------------- problem constants ----------------
#define B_WIN  2048
#define NTOK   49
#define DIMF   256
#define HEADS  8
#define HD     32
#define MROWS  (B_WIN * NTOK)        // 100352
#define QKVCOL 768

#define LOSC   2048.0f               // (wsplit lo kept for layout compat; unused)
#define PSC    512.0f                // attn P-lo pre-scale
#define PSCINV 1.953125e-3f          // 1/512

// ---------------- scratch ----------------
__device__ float g_qkv [MROWS * QKVCOL];
__device__ float g_attn[MROWS * DIMF];      // used as __half buffer (half of it)
__device__ float g_bias[HEADS * 64 * 56];   // padded [8][64][56]; pads stay 0
__device__ float g_scale[HEADS];
__device__ unsigned char g_wq[48 * 16384];  // fp16 hi/lo chunks (hi used)
__device__ unsigned char g_wp[16 * 16384];

// ---------------- helpers ----------------
static __device__ __forceinline__ uint32_t s2u(const void* p) {
    uint32_t a;
    asm("{ .reg .u64 t; cvta.to.shared.u64 t, %1; cvt.u32.u64 %0, t; }" : "=r"(a) : "l"(p));
    return a;
}
static __device__ __forceinline__ uint32_t swz(uint32_t byte_in_row, uint32_t row) {
    return (byte_in_row & ~0x7Fu) | ((byte_in_row & 0x7Fu) ^ ((row & 7u) << 4));
}
static __device__ __forceinline__ uint32_t swz64(uint32_t c, uint32_t row) {
    return (c & 0xFu) | (((((c >> 4) ^ ((row >> 1) & 3u))) & 3u) << 4);
}

#define LDSM_X4(r, a)                                                        \
    asm volatile("ldmatrix.sync.aligned.m8n8.x4.shared.b16 {%0,%1,%2,%3}, [%4];" \
        : "=r"((r)[0]), "=r"((r)[1]), "=r"((r)[2]), "=r"((r)[3]) : "r"(a))
#define LDSM_X4T(r, a)                                                       \
    asm volatile("ldmatrix.sync.aligned.m8n8.x4.trans.shared.b16 {%0,%1,%2,%3}, [%4];" \
        : "=r"((r)[0]), "=r"((r)[1]), "=r"((r)[2]), "=r"((r)[3]) : "r"(a))

#define MMA_BF(c, a, b)                                                      \
    asm volatile("mma.sync.aligned.m16n8k16.row.col.f32.bf16.bf16.f32 "      \
        "{%0,%1,%2,%3}, {%4,%5,%6,%7}, {%8,%9}, {%0,%1,%2,%3};"              \
        : "+f"((c)[0]), "+f"((c)[1]), "+f"((c)[2]), "+f"((c)[3])             \
        : "r"((a)[0]), "r"((a)[1]), "r"((a)[2]), "r"((a)[3]),                \
          "r"((b)[0]), "r"((b)[1]))
#define MMA_FH(c, a, b)                                                      \
    asm volatile("mma.sync.aligned.m16n8k16.row.col.f32.f16.f16.f32 "        \
        "{%0,%1,%2,%3}, {%4,%5,%6,%7}, {%8,%9}, {%0,%1,%2,%3};"              \
        : "+f"((c)[0]), "+f"((c)[1]), "+f"((c)[2]), "+f"((c)[3])             \
        : "r"((a)[0]), "r"((a)[1]), "r"((a)[2]), "r"((a)[3]),                \
          "r"((b)[0]), "r"((b)[1]))
#define MMA_HH(c2, a, b)                                                     \
    asm volatile("mma.sync.aligned.m16n8k16.row.col.f16.f16.f16.f16 "        \
        "{%0,%1}, {%2,%3,%4,%5}, {%6,%7}, {%0,%1};"                          \
        : "+r"((c2)[0]), "+r"((c2)[1])                                       \
        : "r"((a)[0]), "r"((a)[1]), "r"((a)[2]), "r"((a)[3]),                \
          "r"((b)[0]), "r"((b)[1]))

#define CP16(d, s) \
    asm volatile("cp.async.cg.shared.global [%0], [%1], 16;" :: "r"(d), "l"(s) : "memory")
#define CP_COMMIT() asm volatile("cp.async.commit_group;" ::: "memory")
#define CP_WAIT(n)  asm volatile("cp.async.wait_group %0;" :: "n"(n) : "memory")

static __device__ __forceinline__ uint32_t pk2(float x, float y) {   // bf16x2
    uint32_t r;
    asm("cvt.rn.bf16x2.f32 %0, %1, %2;" : "=r"(r) : "f"(y), "f"(x));
    return r;
}
static __device__ __forceinline__ uint32_t pk2h(float x, float y) {  // f16x2
    uint32_t r;
    asm("cvt.rn.f16x2.f32 %0, %1, %2;" : "=r"(r) : "f"(y), "f"(x));
    return r;
}
static __device__ __forceinline__ float rbf(float x) {
    return __bfloat162float(__float2bfloat16_rn(x));
}
static __device__ __forceinline__ float rhf(float x) {
    return __half2float(__float2half_rn(x));
}

// =====================================================================
// Kernel 1: CPB-MLP bias table + logit scale
// =====================================================================
__device__ __forceinline__ float cpb_coord(int i) {
    float x = (float)(i - 6) * (8.0f / 6.0f);
    return copysignf(log1pf(fabsf(x)) * 0.4808983469629878f, x);
}

__global__ void cpb_kernel(const float* __restrict__ logit_scale,
                           const float* __restrict__ w1,
                           const float* __restrict__ b1,
                           const float* __restrict__ w2,
                           float* __restrict__ bias_out,
                           float* __restrict__ scale_out)
{
    __shared__ float table[169][HEADS];
    const int tid = threadIdx.x;

    if (tid < HEADS) {
        float ls = logit_scale[tid];
        ls = fminf(ls, logf(100.0f));
        ls = fmaxf(ls, -100.0f);
        scale_out[tid] = expf(ls);
    }
    for (int e = tid; e < 169; e += blockDim.x) {
        const int i = e / 13, j = e % 13;
        const float c0 = cpb_coord(i);
        const float c1 = cpb_coord(j);
        float acc[HEADS];
#pragma unroll
        for (int hh = 0; hh < HEADS; hh++) acc[hh] = 0.0f;
        for (int kk = 0; kk < 512; kk++) {
            float hpre = c0 * w1[kk] + c1 * w1[512 + kk] + b1[kk];
            float g = 0.5f * hpre * (1.0f + erff(hpre * 0.7071067811865475f));
#pragma unroll
            for (int hh = 0; hh < HEADS; hh++) acc[hh] += g * w2[kk * 8 + hh];
        }
#pragma unroll
        for (int hh = 0; hh < HEADS; hh++) table[e][hh] = acc[hh];
    }
    __syncthreads();

    for (int idx = tid; idx < HEADS * NTOK * NTOK; idx += blockDim.x) {
        const int hh  = idx / (NTOK * NTOK);
        const int rem = idx % (NTOK * NTOK);
        const int r   = rem / NTOK;
        const int c   = rem % NTOK;
        const int dh  = (r / 7) - (c / 7) + 6;
        const int dw  = (r % 7) - (c % 7) + 6;
        const float v = table[dh * 13 + dw][hh];
        bias_out[hh * 3584 + r * 56 + c] = 16.0f / (1.0f + __expf(-v));
    }
}

// =====================================================================
// Kernel 1b: weights fp32 -> fp16 chunks, swizzled (hi at chunk+0)
// =====================================================================
__global__ void wsplit_kernel(const float* __restrict__ wq, const float* __restrict__ wp,
                              unsigned char* __restrict__ oq, unsigned char* __restrict__ op)
{
    const int stride = gridDim.x * blockDim.x;
    const int t0 = blockIdx.x * blockDim.x + threadIdx.x;
    for (int idx = t0; idx < 256 * QKVCOL; idx += stride) {
        const int k = idx / QKVCOL, n = idx % QKVCOL;
        const uint32_t off = (uint32_t)((n >> 7) * 8 + (k >> 5)) * 16384u
                           + (uint32_t)(k & 31) * 256u + swz((uint32_t)(n & 127) * 2u, (uint32_t)k);
        *(__half*)(oq + off) = __float2half_rn(wq[idx]);
    }
    for (int idx = t0; idx < 256 * 256; idx += stride) {
        const int k = idx >> 8, n = idx & 255;
        const uint32_t off = (uint32_t)((n >> 7) * 8 + (k >> 5)) * 16384u
                           + (uint32_t)(k & 31) * 256u + swz((uint32_t)(n & 127) * 2u, (uint32_t)k);
        *(__half*)(op + off) = __float2half_rn(wp[idx]);
    }
}

// =====================================================================
// Kernel 2: fp16 1-product GEMM — 4-chunk superchunks (32 KB hi-only
//   stages, 2-stage double buffer, prefetch distance 1), one sync per
//   superchunk (64 MMAs/warp).  smem: A 32KB + 2x32KB = 96KB, 2 CTAs/SM.
// =====================================================================
#define SMW_OFF 32768
#define GEMM_SMEM (32768 + 2 * 32768)

template<bool AHALF>
__global__ __launch_bounds__(256, 2)
void gemm_mma(const void* __restrict__ Ain, const unsigned char* __restrict__ Wp,
              const float* __restrict__ bias, float* __restrict__ C, int NT)
{
    extern __shared__ char smem[];
    const uint32_t sb = s2u(smem);
    const int tid  = threadIdx.x;
    const int lane = tid & 31;
    const int w    = tid >> 5;
    const int row0 = blockIdx.x * 64;
    const int Ncols = NT * 128;

    // A into swizzled smem (64 rows x 512B)
    if (AHALF) {
        const __half* A16 = (const __half*)Ain;
        for (int i = tid; i < 2048; i += 256) {
            const int r  = i >> 5;
            const int c8 = (i & 31) << 3;
            uint4 v = *(const uint4*)(A16 + (size_t)(row0 + r) * 256 + c8);
            const uint32_t off = (uint32_t)r * 512u + swz((uint32_t)c8 * 2u, (uint32_t)r);
            *(uint4*)(smem + off) = v;
        }
    } else {
        const float* A = (const float*)Ain;
        for (int i = tid; i < 4096; i += 256) {
            const int r  = i >> 6;
            const int c4 = (i & 63) << 2;
            float4 a = *(const float4*)(A + (size_t)(row0 + r) * 256 + c4);
            const uint32_t off = (uint32_t)r * 512u + swz((uint32_t)c4 * 2u, (uint32_t)r);
            uint2 hu; hu.x = pk2h(a.x, a.y); hu.y = pk2h(a.z, a.w);
            *(uint2*)(smem + off) = hu;
        }
    }

    const int wm = w & 1;
    const int wn = w >> 1;
    const int NSC = NT * 2;       // superchunks of 4 k-chunks (8KB hi each)

    // prefetch superchunk 0 into stage 0
    {
#pragma unroll
        for (int c4 = 0; c4 < 4; c4++) {
            const unsigned char* src = Wp + (size_t)c4 * 16384;
            const uint32_t dst = sb + SMW_OFF + (uint32_t)c4 * 8192u;
#pragma unroll
            for (int j = 0; j < 2; j++)
                CP16(dst + (uint32_t)(tid * 16 + j * 4096), src + tid * 16 + j * 4096);
        }
        CP_COMMIT();
    }

    float acc[2][4][4];
    int nt = 0;
#pragma unroll
    for (int mf = 0; mf < 2; mf++)
#pragma unroll
        for (int nf = 0; nf < 4; nf++)
#pragma unroll
            for (int q = 0; q < 4; q++) acc[mf][nf][q] = 0.0f;

    for (int s = 0; s < NSC; s++) {
        CP_WAIT(0);          // superchunk s landed
        __syncthreads();     // all warps done with s-1 (frees stage (s+1)&1)

        if (s + 1 < NSC) {
            const uint32_t stg = sb + SMW_OFF + (uint32_t)((s + 1) & 1) * 32768u;
#pragma unroll
            for (int c4 = 0; c4 < 4; c4++) {
                const unsigned char* src = Wp + (size_t)(4 * (s + 1) + c4) * 16384;
                const uint32_t dst = stg + (uint32_t)c4 * 8192u;
#pragma unroll
                for (int j = 0; j < 2; j++)
                    CP16(dst + (uint32_t)(tid * 16 + j * 4096), src + tid * 16 + j * 4096);
            }
        }
        CP_COMMIT();

        const uint32_t st0 = sb + SMW_OFF + (uint32_t)(s & 1) * 32768u;

#pragma unroll
        for (int c4 = 0; c4 < 4; c4++) {
            const uint32_t st = st0 + (uint32_t)c4 * 8192u;
            const int kc = ((s & 1) << 2) | c4;

#pragma unroll
            for (int ks = 0; ks < 2; ks++) {
                uint32_t ah[2][4];
                const int arow = wm * 32 + ((lane >> 3) & 1) * 8 + (lane & 7);
                const int kg   = kc * 32 + ks * 16 + ((lane >> 4) << 3);
#pragma unroll
                for (int mf = 0; mf < 2; mf++) {
                    const uint32_t r = (uint32_t)(arow + mf * 16);
                    LDSM_X4(ah[mf], sb + r * 512u + swz((uint32_t)kg * 2u, r));
                }
                uint32_t bh[2][4];
                const uint32_t krow = (uint32_t)(ks * 16 + ((lane >> 3) & 1) * 8 + (lane & 7));
#pragma unroll
                for (int nf2 = 0; nf2 < 2; nf2++) {
                    const uint32_t ncol = (uint32_t)(wn * 32 + nf2 * 16 + (lane >> 4) * 8);
                    LDSM_X4T(bh[nf2], st + krow * 256u + swz(ncol * 2u, krow));
                }
#pragma unroll
                for (int mf = 0; mf < 2; mf++)
#pragma unroll
                    for (int nf = 0; nf < 4; nf++)
                        MMA_FH(acc[mf][nf], ah[mf], &bh[nf >> 1][(nf & 1) * 2]);
            }
        }

        if (s & 1) {
            const int g = lane >> 2, t = lane & 3;
#pragma unroll
            for (int nf = 0; nf < 4; nf++) {
                const int col = nt * 128 + wn * 32 + nf * 8 + t * 2;
                const float2 bv = *(const float2*)(bias + col);
#pragma unroll
                for (int mf = 0; mf < 2; mf++) {
                    const int row = row0 + wm * 32 + mf * 16 + g;
                    float2 v0 = make_float2(acc[mf][nf][0] + bv.x, acc[mf][nf][1] + bv.y);
                    float2 v1 = make_float2(acc[mf][nf][2] + bv.x, acc[mf][nf][3] + bv.y);
                    *(float2*)(C + (size_t)row * Ncols + col)       = v0;
                    *(float2*)(C + (size_t)(row + 8) * Ncols + col) = v1;
                }
            }
            nt++;
#pragma unroll
            for (int mf = 0; mf < 2; mf++)
#pragma unroll
                for (int nf = 0; nf < 4; nf++)
#pragma unroll
                    for (int q = 0; q < 4; q++) acc[mf][nf][q] = 0.0f;
        }
    }
}

// =====================================================================
// Kernel 3: tensor-core window attention (unchanged from R15)
// =====================================================================
#define AHEAD 17920
#define AQH 0
#define AQL 3584
#define AKH 7168
#define AKL 10752
#define AVH 14336
#define ATTN_SMEM (4 * AHEAD + 512)

__global__ __launch_bounds__(256, 2)
void attn_tc(const float* __restrict__ qkv,
             const float* __restrict__ bias,
             const float* __restrict__ scale,
             __half* __restrict__ attn_out)
{
    extern __shared__ char smem[];
    const uint32_t sb = s2u(smem);
    const int b    = blockIdx.x;
    const int hg   = blockIdx.y;
    const int tid  = threadIdx.x;
    const int lane = tid & 31;
    const int wrp  = tid >> 5;

    {
        int i = tid;
        if (i < 112) {
            const int slot = i / 28, rem = i % 28;
            const int rr = 49 + rem / 4, c16 = (rem & 3) * 16;
            *(uint4*)(smem + slot * AHEAD + AVH + rr * 64 + c16) = make_uint4(0, 0, 0, 0);
        } else if (i < 144) {
            *(uint4*)(smem + 4 * AHEAD + (i - 112) * 16) = make_uint4(0, 0, 0, 0);
        }
    }

    {
        const float* wb = qkv + (size_t)b * NTOK * QKVCOL;
        const int team = tid >> 2, l4 = tid & 3;
#pragma unroll
        for (int it0 = 0; it0 < 256; it0 += 64) {
            const int it  = it0 + team;
            const bool act = (it < 196);
            const int tok  = act ? (it >> 2) : 0;
            const int slot = it & 3;
            const int hh   = hg * 4 + (act ? slot : 0);
            const float* rowp = wb + (size_t)tok * QKVCOL + hh * HD + l4 * 8;

            float4 q0, q1, k0, k1, v0, v1;
            if (act) {
                q0 = *(const float4*)(rowp);
                q1 = *(const float4*)(rowp + 4);
                k0 = *(const float4*)(rowp + 256);
                k1 = *(const float4*)(rowp + 260);
                v0 = *(const float4*)(rowp + 512);
                v1 = *(const float4*)(rowp + 516);
            } else {
                q0 = q1 = k0 = k1 = v0 = v1 = make_float4(0.f, 0.f, 0.f, 0.f);
            }

            float qss = q0.x*q0.x + q0.y*q0.y + q0.z*q0.z + q0.w*q0.w
                      + q1.x*q1.x + q1.y*q1.y + q1.z*q1.z + q1.w*q1.w;
            float kss = k0.x*k0.x + k0.y*k0.y + k0.z*k0.z + k0.w*k0.w
                      + k1.x*k1.x + k1.y*k1.y + k1.z*k1.z + k1.w*k1.w;
#pragma unroll
            for (int o = 1; o < 4; o <<= 1) {
                qss += __shfl_xor_sync(0xffffffffu, qss, o);
                kss += __shfl_xor_sync(0xffffffffu, kss, o);
            }
            if (act) {
                const float qr = rsqrtf(qss) * __ldg(scale + hh);
                const float kr = rsqrtf(kss);
                q0.x *= qr; q0.y *= qr; q0.z *= qr; q0.w *= qr;
                q1.x *= qr; q1.y *= qr; q1.z *= qr; q1.w *= qr;
                k0.x *= kr; k0.y *= kr; k0.z *= kr; k0.w *= kr;
                k1.x *= kr; k1.y *= kr; k1.z *= kr; k1.w *= kr;

                const uint32_t base = (uint32_t)slot * AHEAD + (uint32_t)tok * 64u
                                    + (uint32_t)((l4 ^ ((tok >> 1) & 3)) << 4);
                {
                    float h0 = rbf(q0.x), h1 = rbf(q0.y), h2 = rbf(q0.z), h3 = rbf(q0.w);
                    float h4 = rbf(q1.x), h5 = rbf(q1.y), h6 = rbf(q1.z), h7 = rbf(q1.w);
                    uint4 hu = make_uint4(pk2(h0,h1), pk2(h2,h3), pk2(h4,h5), pk2(h6,h7));
                    uint4 lu = make_uint4(pk2(q0.x-h0,q0.y-h1), pk2(q0.z-h2,q0.w-h3),
                                          pk2(q1.x-h4,q1.y-h5), pk2(q1.z-h6,q1.w-h7));
                    *(uint4*)(smem + AQH + base) = hu;
                    *(uint4*)(smem + AQL + base) = lu;
                }
                {
                    float h0 = rbf(k0.x), h1 = rbf(k0.y), h2 = rbf(k0.z), h3 = rbf(k0.w);
                    float h4 = rbf(k1.x), h5 = rbf(k1.y), h6 = rbf(k1.z), h7 = rbf(k1.w);
                    uint4 hu = make_uint4(pk2(h0,h1), pk2(h2,h3), pk2(h4,h5), pk2(h6,h7));
                    uint4 lu = make_uint4(pk2(k0.x-h0,k0.y-h1), pk2(k0.z-h2,k0.w-h3),
                                          pk2(k1.x-h4,k1.y-h5), pk2(k1.z-h6,k1.w-h7));
                    *(uint4*)(smem + AKH + base) = hu;
                    *(uint4*)(smem + AKL + base) = lu;
                }
                {
                    uint4 hu = make_uint4(pk2h(v0.x,v0.y), pk2h(v0.z,v0.w),
                                          pk2h(v1.x,v1.y), pk2h(v1.z,v1.w));
                    *(uint4*)(smem + AVH + base) = hu;
                }
            }
        }
    }
    __syncthreads();

    const int slot = wrp >> 1;
    const int h    = hg * 4 + slot;
    const int m0base = (wrp & 1) * 32;
    const uint32_t hb = sb + (uint32_t)slot * AHEAD;
    const float* bslab = bias + h * 3584;
    __half* obase = attn_out + (size_t)b * NTOK * DIMF + h * HD;
    const int qrow = lane >> 2;
    const int qc   = (lane & 3) * 2;

#pragma unroll
    for (int mc = 0; mc < 2; mc++) {
        const int m0 = m0base + mc * 16;
        const int r0 = m0 + qrow;

        float S[7][4];
#pragma unroll
        for (int nf = 0; nf < 7; nf++) {
            const int c0 = nf * 8 + qc;
            const float2 b0 = *(const float2*)(bslab + r0 * 56 + c0);
            const float2 b1 = *(const float2*)(bslab + (r0 + 8) * 56 + c0);
            S[nf][0] = b0.x; S[nf][1] = b0.y;
            S[nf][2] = b1.x; S[nf][3] = b1.y;
        }

#pragma unroll
        for (int ks = 0; ks < 2; ks++) {
            uint32_t ah[4], al[4];
            {
                const uint32_t r = (uint32_t)(m0 + ((lane >> 3) & 1) * 8 + (lane & 7));
                const uint32_t cb = (uint32_t)(ks * 32 + (lane >> 4) * 16);
                const uint32_t ad = hb + AQH + r * 64u + swz64(cb, r);
                LDSM_X4(ah, ad);
                LDSM_X4(al, ad + (AQL - AQH));
            }
#pragma unroll
            for (int ng = 0; ng < 4; ng++) {
                uint32_t bh[4], bl[4];
                const uint32_t r = (uint32_t)(ng * 16 + (lane & 7) + ((lane >> 4) << 3));
                const uint32_t cb = (uint32_t)(ks * 32 + ((lane >> 3) & 1) * 16);
                const uint32_t ad = hb + AKH + r * 64u + swz64(cb, r);
                LDSM_X4(bh, ad);
                LDSM_X4(bl, ad + (AKL - AKH));
                MMA_BF(S[2 * ng], ah, bh);
                MMA_BF(S[2 * ng], ah, bl);
                MMA_BF(S[2 * ng], al, bh);
                if (ng < 3) {
                    MMA_BF(S[2 * ng + 1], ah, bh + 2);
                    MMA_BF(S[2 * ng + 1], ah, bl + 2);
                    MMA_BF(S[2 * ng + 1], al, bh + 2);
                }
            }
        }

        {
            float mx0 = -1e30f, mx1 = -1e30f;
#pragma unroll
            for (int nf = 0; nf < 7; nf++) {
                const int c0 = nf * 8 + qc;
                S[nf][0] = (c0     < 49) ? S[nf][0] : -1e30f;
                S[nf][1] = (c0 + 1 < 49) ? S[nf][1] : -1e30f;
                S[nf][2] = (c0     < 49) ? S[nf][2] : -1e30f;
                S[nf][3] = (c0 + 1 < 49) ? S[nf][3] : -1e30f;
                mx0 = fmaxf(mx0, fmaxf(S[nf][0], S[nf][1]));
                mx1 = fmaxf(mx1, fmaxf(S[nf][2], S[nf][3]));
            }
#pragma unroll
            for (int o = 1; o < 4; o <<= 1) {
                mx0 = fmaxf(mx0, __shfl_xor_sync(0xffffffffu, mx0, o));
                mx1 = fmaxf(mx1, __shfl_xor_sync(0xffffffffu, mx1, o));
            }
            float rs0 = 0.0f, rs1 = 0.0f;
#pragma unroll
            for (int nf = 0; nf < 7; nf++) {
                float p0 = __expf(S[nf][0] - mx0);
                float p1 = __expf(S[nf][1] - mx0);
                float p2 = __expf(S[nf][2] - mx1);
                float p3 = __expf(S[nf][3] - mx1);
                S[nf][0] = p0; S[nf][1] = p1; S[nf][2] = p2; S[nf][3] = p3;
                rs0 += p0 + p1;  rs1 += p2 + p3;
            }
#pragma unroll
            for (int o = 1; o < 4; o <<= 1) {
                rs0 += __shfl_xor_sync(0xffffffffu, rs0, o);
                rs1 += __shfl_xor_sync(0xffffffffu, rs1, o);
            }
            const float iv0 = 1.0f / rs0, iv1 = 1.0f / rs1;
#pragma unroll
            for (int nf = 0; nf < 7; nf++) {
                S[nf][0] *= iv0; S[nf][1] *= iv0;
                S[nf][2] *= iv1; S[nf][3] *= iv1;
            }
        }

        float O[4][4];
        uint32_t Olo[4][2];
#pragma unroll
        for (int n = 0; n < 4; n++) {
#pragma unroll
            for (int q = 0; q < 4; q++) O[n][q] = 0.0f;
            Olo[n][0] = 0u; Olo[n][1] = 0u;
        }

#pragma unroll
        for (int kt = 0; kt < 4; kt++) {
            uint32_t ph[4], pl[4];
            {
                float pa0 = S[2*kt][0], pa1 = S[2*kt][1], pa2 = S[2*kt][2], pa3 = S[2*kt][3];
                float pb0 = 0.f, pb1 = 0.f, pb2 = 0.f, pb3 = 0.f;
                if (kt < 3) {
                    pb0 = S[2*kt+1][0]; pb1 = S[2*kt+1][1];
                    pb2 = S[2*kt+1][2]; pb3 = S[2*kt+1][3];
                }
                const float ha0 = rhf(pa0), ha1 = rhf(pa1), ha2 = rhf(pa2), ha3 = rhf(pa3);
                const float hb0 = rhf(pb0), hb1 = rhf(pb1), hb2 = rhf(pb2), hb3 = rhf(pb3);
                ph[0] = pk2h(ha0, ha1);  ph[1] = pk2h(ha2, ha3);
                ph[2] = pk2h(hb0, hb1);  ph[3] = pk2h(hb2, hb3);
                pl[0] = pk2h((pa0 - ha0) * PSC, (pa1 - ha1) * PSC);
                pl[1] = pk2h((pa2 - ha2) * PSC, (pa3 - ha3) * PSC);
                pl[2] = pk2h((pb0 - hb0) * PSC, (pb1 - hb1) * PSC);
                pl[3] = pk2h((pb2 - hb2) * PSC, (pb3 - hb3) * PSC);
            }
#pragma unroll
            for (int vg = 0; vg < 2; vg++) {
                uint32_t vh[4];
                const uint32_t kr = (uint32_t)(kt * 16 + ((lane >> 3) & 1) * 8 + (lane & 7));
                const uint32_t cb = (uint32_t)(vg * 32 + (lane >> 4) * 16);
                LDSM_X4T(vh, hb + AVH + kr * 64u + swz64(cb, kr));
#pragma unroll
                for (int nn = 0; nn < 2; nn++) {
                    MMA_FH(O[vg * 2 + nn], ph, vh + nn * 2);
                    MMA_HH(Olo[vg * 2 + nn], pl, vh + nn * 2);
                }
            }
        }

        {
#pragma unroll
            for (int nf = 0; nf < 4; nf++) {
                const int c = nf * 8 + qc;
                float2 c01 = __half22float2(*(const __half2*)&Olo[nf][0]);
                float2 c23 = __half22float2(*(const __half2*)&Olo[nf][1]);
                if (r0 < NTOK)
                    *(uint32_t*)(obase + (size_t)r0 * DIMF + c) =
                        pk2h(O[nf][0] + c01.x * PSCINV, O[nf][1] + c01.y * PSCINV);
                if (r0 + 8 < NTOK)
                    *(uint32_t*)(obase + (size_t)(r0 + 8) * DIMF + c) =
                        pk2h(O[nf][2] + c23.x * PSCINV, O[nf][3] + c23.y * PSCINV);
            }
        }
    }
}

// =====================================================================
// launch
// =====================================================================
extern "C" void kernel_launch(void* const* d_in, const int* in_sizes, int n_in,
                              void* d_out, int out_size)
{
    const float* x           = (const float*)d_in[0];
    const float* qkv_w       = (const float*)d_in[1];
    const float* qkv_b       = (const float*)d_in[2];
    const float* proj_w      = (const float*)d_in[3];
    const float* proj_b      = (const float*)d_in[4];
    const float* logit_scale = (const float*)d_in[5];
    const float* cpb_w1      = (const float*)d_in[6];
    const float* cpb_b1      = (const float*)d_in[7];
    const float* cpb_w2      = (const float*)d_in[8];
    float* out = (float*)d_out;

    float *qkvbuf, *attnbuf, *biasbuf, *scalebuf;
    unsigned char *wqbuf, *wpbuf;
    cudaGetSymbolAddress((void**)&qkvbuf,   g_qkv);
    cudaGetSymbolAddress((void**)&attnbuf,  g_attn);
    cudaGetSymbolAddress((void**)&biasbuf,  g_bias);
    cudaGetSymbolAddress((void**)&scalebuf, g_scale);
    cudaGetSymbolAddress((void**)&wqbuf,    g_wq);
    cudaGetSymbolAddress((void**)&wpbuf,    g_wp);

    cudaFuncSetAttribute((const void*)gemm_mma<false>,
                         cudaFuncAttributeMaxDynamicSharedMemorySize, GEMM_SMEM);
    cudaFuncSetAttribute((const void*)gemm_mma<true>,
                         cudaFuncAttributeMaxDynamicSharedMemorySize, GEMM_SMEM);
    cudaFuncSetAttribute((const void*)attn_tc,
                         cudaFuncAttributeMaxDynamicSharedMemorySize, ATTN_SMEM);

    cpb_kernel<<<1, 256>>>(logit_scale, cpb_w1, cpb_b1, cpb_w2, biasbuf, scalebuf);
    wsplit_kernel<<<128, 256>>>(qkv_w, proj_w, wqbuf, wpbuf);

    gemm_mma<false><<<MROWS / 64, 256, GEMM_SMEM>>>(x, wqbuf, qkv_b, qkvbuf, 6);

    attn_tc<<<dim3(B_WIN, 2), 256, ATTN_SMEM>>>(qkvbuf, biasbuf, scalebuf,
                                                (__half*)attnbuf);

    gemm_mma<true><<<MROWS / 64, 256, GEMM_SMEM>>>(attnbuf, wpbuf, proj_b, out, 2);
}

// round 17
// speedup vs baseline: 1.2644x; 1.0499x over previous
#include <cuda_runtime.h>
#include <cuda_bf16.h>
#include <cuda_fp16.h>
#include <cstdint>

// ---------------- problem constants ----------------
#define B_WIN  2048
#define NTOK   49
#define DIMF   256
#define HEADS  8
#define HD     32
#define MROWS  (B_WIN * NTOK)        // 100352
#define QKVCOL 768

#define PSC    512.0f                // attn P-lo pre-scale
#define PSCINV 1.953125e-3f          // 1/512

// ---------------- scratch ----------------
__device__ float g_qkv [MROWS * QKVCOL / 2];   // fp16 [B*49, 768]
__device__ float g_attn[MROWS * DIMF];          // fp16 used in low half
__device__ float g_bias[HEADS * 64 * 56];       // padded [8][64][56]; pads 0
__device__ float g_scale[HEADS];
__device__ unsigned char g_wq[48 * 16384];      // fp16 chunks
__device__ unsigned char g_wp[16 * 16384];

// ---------------- helpers ----------------
static __device__ __forceinline__ uint32_t s2u(const void* p) {
    uint32_t a;
    asm("{ .reg .u64 t; cvta.to.shared.u64 t, %1; cvt.u32.u64 %0, t; }" : "=r"(a) : "l"(p));
    return a;
}
static __device__ __forceinline__ uint32_t swz(uint32_t byte_in_row, uint32_t row) {
    return (byte_in_row & ~0x7Fu) | ((byte_in_row & 0x7Fu) ^ ((row & 7u) << 4));
}
static __device__ __forceinline__ uint32_t swz64(uint32_t c, uint32_t row) {
    return (c & 0xFu) | (((((c >> 4) ^ ((row >> 1) & 3u))) & 3u) << 4);
}

#define LDSM_X4(r, a)                                                        \
    asm volatile("ldmatrix.sync.aligned.m8n8.x4.shared.b16 {%0,%1,%2,%3}, [%4];" \
        : "=r"((r)[0]), "=r"((r)[1]), "=r"((r)[2]), "=r"((r)[3]) : "r"(a))
#define LDSM_X4T(r, a)                                                       \
    asm volatile("ldmatrix.sync.aligned.m8n8.x4.trans.shared.b16 {%0,%1,%2,%3}, [%4];" \
        : "=r"((r)[0]), "=r"((r)[1]), "=r"((r)[2]), "=r"((r)[3]) : "r"(a))

#define MMA_BF(c, a, b)                                                      \
    asm volatile("mma.sync.aligned.m16n8k16.row.col.f32.bf16.bf16.f32 "      \
        "{%0,%1,%2,%3}, {%4,%5,%6,%7}, {%8,%9}, {%0,%1,%2,%3};"              \
        : "+f"((c)[0]), "+f"((c)[1]), "+f"((c)[2]), "+f"((c)[3])             \
        : "r"((a)[0]), "r"((a)[1]), "r"((a)[2]), "r"((a)[3]),                \
          "r"((b)[0]), "r"((b)[1]))
#define MMA_FH(c, a, b)                                                      \
    asm volatile("mma.sync.aligned.m16n8k16.row.col.f32.f16.f16.f32 "        \
        "{%0,%1,%2,%3}, {%4,%5,%6,%7}, {%8,%9}, {%0,%1,%2,%3};"              \
        : "+f"((c)[0]), "+f"((c)[1]), "+f"((c)[2]), "+f"((c)[3])             \
        : "r"((a)[0]), "r"((a)[1]), "r"((a)[2]), "r"((a)[3]),                \
          "r"((b)[0]), "r"((b)[1]))
#define MMA_HH(c2, a, b)                                                     \
    asm volatile("mma.sync.aligned.m16n8k16.row.col.f16.f16.f16.f16 "        \
        "{%0,%1}, {%2,%3,%4,%5}, {%6,%7}, {%0,%1};"                          \
        : "+r"((c2)[0]), "+r"((c2)[1])                                       \
        : "r"((a)[0]), "r"((a)[1]), "r"((a)[2]), "r"((a)[3]),                \
          "r"((b)[0]), "r"((b)[1]))

#define CP16(d, s) \
    asm volatile("cp.async.cg.shared.global [%0], [%1], 16;" :: "r"(d), "l"(s) : "memory")
#define CP_COMMIT() asm volatile("cp.async.commit_group;" ::: "memory")
#define CP_WAIT(n)  asm volatile("cp.async.wait_group %0;" :: "n"(n) : "memory")

static __device__ __forceinline__ uint32_t pk2(float x, float y) {   // bf16x2
    uint32_t r;
    asm("cvt.rn.bf16x2.f32 %0, %1, %2;" : "=r"(r) : "f"(y), "f"(x));
    return r;
}
static __device__ __forceinline__ uint32_t pk2h(float x, float y) {  // f16x2
    uint32_t r;
    asm("cvt.rn.f16x2.f32 %0, %1, %2;" : "=r"(r) : "f"(y), "f"(x));
    return r;
}
static __device__ __forceinline__ float rbf(float x) {
    return __bfloat162float(__float2bfloat16_rn(x));
}
static __device__ __forceinline__ float rhf(float x) {
    return __half2float(__float2half_rn(x));
}

// =====================================================================
// Kernel 1: CPB-MLP bias table + logit scale
// =====================================================================
__device__ __forceinline__ float cpb_coord(int i) {
    float x = (float)(i - 6) * (8.0f / 6.0f);
    return copysignf(log1pf(fabsf(x)) * 0.4808983469629878f, x);
}

__global__ void cpb_kernel(const float* __restrict__ logit_scale,
                           const float* __restrict__ w1,
                           const float* __restrict__ b1,
                           const float* __restrict__ w2,
                           float* __restrict__ bias_out,
                           float* __restrict__ scale_out)
{
    __shared__ float table[169][HEADS];
    const int tid = threadIdx.x;

    if (tid < HEADS) {
        float ls = logit_scale[tid];
        ls = fminf(ls, logf(100.0f));
        ls = fmaxf(ls, -100.0f);
        scale_out[tid] = expf(ls);
    }
    for (int e = tid; e < 169; e += blockDim.x) {
        const int i = e / 13, j = e % 13;
        const float c0 = cpb_coord(i);
        const float c1 = cpb_coord(j);
        float acc[HEADS];
#pragma unroll
        for (int hh = 0; hh < HEADS; hh++) acc[hh] = 0.0f;
        for (int kk = 0; kk < 512; kk++) {
            float hpre = c0 * w1[kk] + c1 * w1[512 + kk] + b1[kk];
            float g = 0.5f * hpre * (1.0f + erff(hpre * 0.7071067811865475f));
#pragma unroll
            for (int hh = 0; hh < HEADS; hh++) acc[hh] += g * w2[kk * 8 + hh];
        }
#pragma unroll
        for (int hh = 0; hh < HEADS; hh++) table[e][hh] = acc[hh];
    }
    __syncthreads();

    for (int idx = tid; idx < HEADS * NTOK * NTOK; idx += blockDim.x) {
        const int hh  = idx / (NTOK * NTOK);
        const int rem = idx % (NTOK * NTOK);
        const int r   = rem / NTOK;
        const int c   = rem % NTOK;
        const int dh  = (r / 7) - (c / 7) + 6;
        const int dw  = (r % 7) - (c % 7) + 6;
        const float v = table[dh * 13 + dw][hh];
        bias_out[hh * 3584 + r * 56 + c] = 16.0f / (1.0f + __expf(-v));
    }
}

// =====================================================================
// Kernel 1b: weights fp32 -> fp16 chunks, swizzled
// =====================================================================
__global__ void wsplit_kernel(const float* __restrict__ wq, const float* __restrict__ wp,
                              unsigned char* __restrict__ oq, unsigned char* __restrict__ op)
{
    const int stride = gridDim.x * blockDim.x;
    const int t0 = blockIdx.x * blockDim.x + threadIdx.x;
    for (int idx = t0; idx < 256 * QKVCOL; idx += stride) {
        const int k = idx / QKVCOL, n = idx % QKVCOL;
        const uint32_t off = (uint32_t)((n >> 7) * 8 + (k >> 5)) * 16384u
                           + (uint32_t)(k & 31) * 256u + swz((uint32_t)(n & 127) * 2u, (uint32_t)k);
        *(__half*)(oq + off) = __float2half_rn(wq[idx]);
    }
    for (int idx = t0; idx < 256 * 256; idx += stride) {
        const int k = idx >> 8, n = idx & 255;
        const uint32_t off = (uint32_t)((n >> 7) * 8 + (k >> 5)) * 16384u
                           + (uint32_t)(k & 31) * 256u + swz((uint32_t)(n & 127) * 2u, (uint32_t)k);
        *(__half*)(op + off) = __float2half_rn(wp[idx]);
    }
}

// =====================================================================
// Kernel 2: fp16 1-product GEMM — 4-chunk superchunks, 2-stage ring.
//   AHALF: A already fp16.  OUTHALF: store C as fp16.
// =====================================================================
#define SMW_OFF 32768
#define GEMM_SMEM (32768 + 2 * 32768)

template<bool AHALF, bool OUTHALF>
__global__ __launch_bounds__(256, 2)
void gemm_mma(const void* __restrict__ Ain, const unsigned char* __restrict__ Wp,
              const float* __restrict__ bias, void* __restrict__ Cout, int NT)
{
    extern __shared__ char smem[];
    const uint32_t sb = s2u(smem);
    const int tid  = threadIdx.x;
    const int lane = tid & 31;
    const int w    = tid >> 5;
    const int row0 = blockIdx.x * 64;
    const int Ncols = NT * 128;

    if (AHALF) {
        const __half* A16 = (const __half*)Ain;
        for (int i = tid; i < 2048; i += 256) {
            const int r  = i >> 5;
            const int c8 = (i & 31) << 3;
            uint4 v = *(const uint4*)(A16 + (size_t)(row0 + r) * 256 + c8);
            const uint32_t off = (uint32_t)r * 512u + swz((uint32_t)c8 * 2u, (uint32_t)r);
            *(uint4*)(smem + off) = v;
        }
    } else {
        const float* A = (const float*)Ain;
        for (int i = tid; i < 4096; i += 256) {
            const int r  = i >> 6;
            const int c4 = (i & 63) << 2;
            float4 a = *(const float4*)(A + (size_t)(row0 + r) * 256 + c4);
            const uint32_t off = (uint32_t)r * 512u + swz((uint32_t)c4 * 2u, (uint32_t)r);
            uint2 hu; hu.x = pk2h(a.x, a.y); hu.y = pk2h(a.z, a.w);
            *(uint2*)(smem + off) = hu;
        }
    }

    const int wm = w & 1;
    const int wn = w >> 1;
    const int NSC = NT * 2;

    {
#pragma unroll
        for (int c4 = 0; c4 < 4; c4++) {
            const unsigned char* src = Wp + (size_t)c4 * 16384;
            const uint32_t dst = sb + SMW_OFF + (uint32_t)c4 * 8192u;
#pragma unroll
            for (int j = 0; j < 2; j++)
                CP16(dst + (uint32_t)(tid * 16 + j * 4096), src + tid * 16 + j * 4096);
        }
        CP_COMMIT();
    }

    float acc[2][4][4];
    int nt = 0;
#pragma unroll
    for (int mf = 0; mf < 2; mf++)
#pragma unroll
        for (int nf = 0; nf < 4; nf++)
#pragma unroll
            for (int q = 0; q < 4; q++) acc[mf][nf][q] = 0.0f;

    for (int s = 0; s < NSC; s++) {
        CP_WAIT(0);
        __syncthreads();

        if (s + 1 < NSC) {
            const uint32_t stg = sb + SMW_OFF + (uint32_t)((s + 1) & 1) * 32768u;
#pragma unroll
            for (int c4 = 0; c4 < 4; c4++) {
                const unsigned char* src = Wp + (size_t)(4 * (s + 1) + c4) * 16384;
                const uint32_t dst = stg + (uint32_t)c4 * 8192u;
#pragma unroll
                for (int j = 0; j < 2; j++)
                    CP16(dst + (uint32_t)(tid * 16 + j * 4096), src + tid * 16 + j * 4096);
            }
        }
        CP_COMMIT();

        const uint32_t st0 = sb + SMW_OFF + (uint32_t)(s & 1) * 32768u;

#pragma unroll
        for (int c4 = 0; c4 < 4; c4++) {
            const uint32_t st = st0 + (uint32_t)c4 * 8192u;
            const int kc = ((s & 1) << 2) | c4;

#pragma unroll
            for (int ks = 0; ks < 2; ks++) {
                uint32_t ah[2][4];
                const int arow = wm * 32 + ((lane >> 3) & 1) * 8 + (lane & 7);
                const int kg   = kc * 32 + ks * 16 + ((lane >> 4) << 3);
#pragma unroll
                for (int mf = 0; mf < 2; mf++) {
                    const uint32_t r = (uint32_t)(arow + mf * 16);
                    LDSM_X4(ah[mf], sb + r * 512u + swz((uint32_t)kg * 2u, r));
                }
                uint32_t bh[2][4];
                const uint32_t krow = (uint32_t)(ks * 16 + ((lane >> 3) & 1) * 8 + (lane & 7));
#pragma unroll
                for (int nf2 = 0; nf2 < 2; nf2++) {
                    const uint32_t ncol = (uint32_t)(wn * 32 + nf2 * 16 + (lane >> 4) * 8);
                    LDSM_X4T(bh[nf2], st + krow * 256u + swz(ncol * 2u, krow));
                }
#pragma unroll
                for (int mf = 0; mf < 2; mf++)
#pragma unroll
                    for (int nf = 0; nf < 4; nf++)
                        MMA_FH(acc[mf][nf], ah[mf], &bh[nf >> 1][(nf & 1) * 2]);
            }
        }

        if (s & 1) {
            const int g = lane >> 2, t = lane & 3;
#pragma unroll
            for (int nf = 0; nf < 4; nf++) {
                const int col = nt * 128 + wn * 32 + nf * 8 + t * 2;
                const float2 bv = *(const float2*)(bias + col);
#pragma unroll
                for (int mf = 0; mf < 2; mf++) {
                    const int row = row0 + wm * 32 + mf * 16 + g;
                    if (OUTHALF) {
                        __half* C = (__half*)Cout;
                        *(uint32_t*)(C + (size_t)row * Ncols + col) =
                            pk2h(acc[mf][nf][0] + bv.x, acc[mf][nf][1] + bv.y);
                        *(uint32_t*)(C + (size_t)(row + 8) * Ncols + col) =
                            pk2h(acc[mf][nf][2] + bv.x, acc[mf][nf][3] + bv.y);
                    } else {
                        float* C = (float*)Cout;
                        *(float2*)(C + (size_t)row * Ncols + col) =
                            make_float2(acc[mf][nf][0] + bv.x, acc[mf][nf][1] + bv.y);
                        *(float2*)(C + (size_t)(row + 8) * Ncols + col) =
                            make_float2(acc[mf][nf][2] + bv.x, acc[mf][nf][3] + bv.y);
                    }
                }
            }
            nt++;
#pragma unroll
            for (int mf = 0; mf < 2; mf++)
#pragma unroll
                for (int nf = 0; nf < 4; nf++)
#pragma unroll
                    for (int q = 0; q < 4; q++) acc[mf][nf][q] = 0.0f;
        }
    }
}

// =====================================================================
// Kernel 3: tensor-core window attention — fp16 qkv input.
// =====================================================================
#define AHEAD 17920
#define AQH 0
#define AQL 3584
#define AKH 7168
#define AKL 10752
#define AVH 14336
#define ATTN_SMEM (4 * AHEAD + 512)

__global__ __launch_bounds__(256, 2)
void attn_tc(const __half* __restrict__ qkv,
             const float* __restrict__ bias,
             const float* __restrict__ scale,
             __half* __restrict__ attn_out)
{
    extern __shared__ char smem[];
    const uint32_t sb = s2u(smem);
    const int b    = blockIdx.x;
    const int hg   = blockIdx.y;
    const int tid  = threadIdx.x;
    const int lane = tid & 31;
    const int wrp  = tid >> 5;

    {
        int i = tid;
        if (i < 112) {
            const int slot = i / 28, rem = i % 28;
            const int rr = 49 + rem / 4, c16 = (rem & 3) * 16;
            *(uint4*)(smem + slot * AHEAD + AVH + rr * 64 + c16) = make_uint4(0, 0, 0, 0);
        } else if (i < 144) {
            *(uint4*)(smem + 4 * AHEAD + (i - 112) * 16) = make_uint4(0, 0, 0, 0);
        }
    }

    // loader: 4-thread teams, each thread owns 8 dims (one uint4 per tensor)
    {
        const __half* wb = qkv + (size_t)b * NTOK * QKVCOL;
        const int team = tid >> 2, l4 = tid & 3;
#pragma unroll
        for (int it0 = 0; it0 < 256; it0 += 64) {
            const int it  = it0 + team;
            const bool act = (it < 196);
            const int tok  = act ? (it >> 2) : 0;
            const int slot = it & 3;
            const int hh   = hg * 4 + (act ? slot : 0);
            const __half* rowp = wb + (size_t)tok * QKVCOL + hh * HD + l4 * 8;

            float4 q0, q1, k0, k1, v0, v1;
            if (act) {
                uint4 qu = *(const uint4*)(rowp);
                uint4 ku = *(const uint4*)(rowp + 256);
                uint4 vu = *(const uint4*)(rowp + 512);
                float2 t;
                t = __half22float2(*(__half2*)&qu.x); q0.x = t.x; q0.y = t.y;
                t = __half22float2(*(__half2*)&qu.y); q0.z = t.x; q0.w = t.y;
                t = __half22float2(*(__half2*)&qu.z); q1.x = t.x; q1.y = t.y;
                t = __half22float2(*(__half2*)&qu.w); q1.z = t.x; q1.w = t.y;
                t = __half22float2(*(__half2*)&ku.x); k0.x = t.x; k0.y = t.y;
                t = __half22float2(*(__half2*)&ku.y); k0.z = t.x; k0.w = t.y;
                t = __half22float2(*(__half2*)&ku.z); k1.x = t.x; k1.y = t.y;
                t = __half22float2(*(__half2*)&ku.w); k1.z = t.x; k1.w = t.y;
                t = __half22float2(*(__half2*)&vu.x); v0.x = t.x; v0.y = t.y;
                t = __half22float2(*(__half2*)&vu.y); v0.z = t.x; v0.w = t.y;
                t = __half22float2(*(__half2*)&vu.z); v1.x = t.x; v1.y = t.y;
                t = __half22float2(*(__half2*)&vu.w); v1.z = t.x; v1.w = t.y;
            } else {
                q0 = q1 = k0 = k1 = v0 = v1 = make_float4(0.f, 0.f, 0.f, 0.f);
            }

            float qss = q0.x*q0.x + q0.y*q0.y + q0.z*q0.z + q0.w*q0.w
                      + q1.x*q1.x + q1.y*q1.y + q1.z*q1.z + q1.w*q1.w;
            float kss = k0.x*k0.x + k0.y*k0.y + k0.z*k0.z + k0.w*k0.w
                      + k1.x*k1.x + k1.y*k1.y + k1.z*k1.z + k1.w*k1.w;
#pragma unroll
            for (int o = 1; o < 4; o <<= 1) {
                qss += __shfl_xor_sync(0xffffffffu, qss, o);
                kss += __shfl_xor_sync(0xffffffffu, kss, o);
            }
            if (act) {
                const float qr = rsqrtf(qss) * __ldg(scale + hh);
                const float kr = rsqrtf(kss);
                q0.x *= qr; q0.y *= qr; q0.z *= qr; q0.w *= qr;
                q1.x *= qr; q1.y *= qr; q1.z *= qr; q1.w *= qr;
                k0.x *= kr; k0.y *= kr; k0.z *= kr; k0.w *= kr;
                k1.x *= kr; k1.y *= kr; k1.z *= kr; k1.w *= kr;

                const uint32_t base = (uint32_t)slot * AHEAD + (uint32_t)tok * 64u
                                    + (uint32_t)((l4 ^ ((tok >> 1) & 3)) << 4);
                {
                    float h0 = rbf(q0.x), h1 = rbf(q0.y), h2 = rbf(q0.z), h3 = rbf(q0.w);
                    float h4 = rbf(q1.x), h5 = rbf(q1.y), h6 = rbf(q1.z), h7 = rbf(q1.w);
                    uint4 hu = make_uint4(pk2(h0,h1), pk2(h2,h3), pk2(h4,h5), pk2(h6,h7));
                    uint4 lu = make_uint4(pk2(q0.x-h0,q0.y-h1), pk2(q0.z-h2,q0.w-h3),
                                          pk2(q1.x-h4,q1.y-h5), pk2(q1.z-h6,q1.w-h7));
                    *(uint4*)(smem + AQH + base) = hu;
                    *(uint4*)(smem + AQL + base) = lu;
                }
                {
                    float h0 = rbf(k0.x), h1 = rbf(k0.y), h2 = rbf(k0.z), h3 = rbf(k0.w);
                    float h4 = rbf(k1.x), h5 = rbf(k1.y), h6 = rbf(k1.z), h7 = rbf(k1.w);
                    uint4 hu = make_uint4(pk2(h0,h1), pk2(h2,h3), pk2(h4,h5), pk2(h6,h7));
                    uint4 lu = make_uint4(pk2(k0.x-h0,k0.y-h1), pk2(k0.z-h2,k0.w-h3),
                                          pk2(k1.x-h4,k1.y-h5), pk2(k1.z-h6,k1.w-h7));
                    *(uint4*)(smem + AKH + base) = hu;
                    *(uint4*)(smem + AKL + base) = lu;
                }
                {
                    uint4 hu = make_uint4(pk2h(v0.x,v0.y), pk2h(v0.z,v0.w),
                                          pk2h(v1.x,v1.y), pk2h(v1.z,v1.w));
                    *(uint4*)(smem + AVH + base) = hu;
                }
            }
        }
    }
    __syncthreads();

    const int slot = wrp >> 1;
    const int h    = hg * 4 + slot;
    const int m0base = (wrp & 1) * 32;
    const uint32_t hb = sb + (uint32_t)slot * AHEAD;
    const float* bslab = bias + h * 3584;
    __half* obase = attn_out + (size_t)b * NTOK * DIMF + h * HD;
    const int qrow = lane >> 2;
    const int qc   = (lane & 3) * 2;

#pragma unroll
    for (int mc = 0; mc < 2; mc++) {
        const int m0 = m0base + mc * 16;
        const int r0 = m0 + qrow;

        float S[7][4];
#pragma unroll
        for (int nf = 0; nf < 7; nf++) {
            const int c0 = nf * 8 + qc;
            const float2 b0 = *(const float2*)(bslab + r0 * 56 + c0);
            const float2 b1 = *(const float2*)(bslab + (r0 + 8) * 56 + c0);
            S[nf][0] = b0.x; S[nf][1] = b0.y;
            S[nf][2] = b1.x; S[nf][3] = b1.y;
        }

#pragma unroll
        for (int ks = 0; ks < 2; ks++) {
            uint32_t ah[4], al[4];
            {
                const uint32_t r = (uint32_t)(m0 + ((lane >> 3) & 1) * 8 + (lane & 7));
                const uint32_t cb = (uint32_t)(ks * 32 + (lane >> 4) * 16);
                const uint32_t ad = hb + AQH + r * 64u + swz64(cb, r);
                LDSM_X4(ah, ad);
                LDSM_X4(al, ad + (AQL - AQH));
            }
#pragma unroll
            for (int ng = 0; ng < 4; ng++) {
                uint32_t bh[4], bl[4];
                const uint32_t r = (uint32_t)(ng * 16 + (lane & 7) + ((lane >> 4) << 3));
                const uint32_t cb = (uint32_t)(ks * 32 + ((lane >> 3) & 1) * 16);
                const uint32_t ad = hb + AKH + r * 64u + swz64(cb, r);
                LDSM_X4(bh, ad);
                LDSM_X4(bl, ad + (AKL - AKH));
                MMA_BF(S[2 * ng], ah, bh);
                MMA_BF(S[2 * ng], ah, bl);
                MMA_BF(S[2 * ng], al, bh);
                if (ng < 3) {
                    MMA_BF(S[2 * ng + 1], ah, bh + 2);
                    MMA_BF(S[2 * ng + 1], ah, bl + 2);
                    MMA_BF(S[2 * ng + 1], al, bh + 2);
                }
            }
        }

        {
            float mx0 = -1e30f, mx1 = -1e30f;
#pragma unroll
            for (int nf = 0; nf < 7; nf++) {
                const int c0 = nf * 8 + qc;
                S[nf][0] = (c0     < 49) ? S[nf][0] : -1e30f;
                S[nf][1] = (c0 + 1 < 49) ? S[nf][1] : -1e30f;
                S[nf][2] = (c0     < 49) ? S[nf][2] : -1e30f;
                S[nf][3] = (c0 + 1 < 49) ? S[nf][3] : -1e30f;
                mx0 = fmaxf(mx0, fmaxf(S[nf][0], S[nf][1]));
                mx1 = fmaxf(mx1, fmaxf(S[nf][2], S[nf][3]));
            }
#pragma unroll
            for (int o = 1; o < 4; o <<= 1) {
                mx0 = fmaxf(mx0, __shfl_xor_sync(0xffffffffu, mx0, o));
                mx1 = fmaxf(mx1, __shfl_xor_sync(0xffffffffu, mx1, o));
            }
            float rs0 = 0.0f, rs1 = 0.0f;
#pragma unroll
            for (int nf = 0; nf < 7; nf++) {
                float p0 = __expf(S[nf][0] - mx0);
                float p1 = __expf(S[nf][1] - mx0);
                float p2 = __expf(S[nf][2] - mx1);
                float p3 = __expf(S[nf][3] - mx1);
                S[nf][0] = p0; S[nf][1] = p1; S[nf][2] = p2; S[nf][3] = p3;
                rs0 += p0 + p1;  rs1 += p2 + p3;
            }
#pragma unroll
            for (int o = 1; o < 4; o <<= 1) {
                rs0 += __shfl_xor_sync(0xffffffffu, rs0, o);
                rs1 += __shfl_xor_sync(0xffffffffu, rs1, o);
            }
            const float iv0 = 1.0f / rs0, iv1 = 1.0f / rs1;
#pragma unroll
            for (int nf = 0; nf < 7; nf++) {
                S[nf][0] *= iv0; S[nf][1] *= iv0;
                S[nf][2] *= iv1; S[nf][3] *= iv1;
            }
        }

        float O[4][4];
        uint32_t Olo[4][2];
#pragma unroll
        for (int n = 0; n < 4; n++) {
#pragma unroll
            for (int q = 0; q < 4; q++) O[n][q] = 0.0f;
            Olo[n][0] = 0u; Olo[n][1] = 0u;
        }

#pragma unroll
        for (int kt = 0; kt < 4; kt++) {
            uint32_t ph[4], pl[4];
            {
                float pa0 = S[2*kt][0], pa1 = S[2*kt][1], pa2 = S[2*kt][2], pa3 = S[2*kt][3];
                float pb0 = 0.f, pb1 = 0.f, pb2 = 0.f, pb3 = 0.f;
                if (kt < 3) {
                    pb0 = S[2*kt+1][0]; pb1 = S[2*kt+1][1];
                    pb2 = S[2*kt+1][2]; pb3 = S[2*kt+1][3];
                }
                const float ha0 = rhf(pa0), ha1 = rhf(pa1), ha2 = rhf(pa2), ha3 = rhf(pa3);
                const float hb0 = rhf(pb0), hb1 = rhf(pb1), hb2 = rhf(pb2), hb3 = rhf(pb3);
                ph[0] = pk2h(ha0, ha1);  ph[1] = pk2h(ha2, ha3);
                ph[2] = pk2h(hb0, hb1);  ph[3] = pk2h(hb2, hb3);
                pl[0] = pk2h((pa0 - ha0) * PSC, (pa1 - ha1) * PSC);
                pl[1] = pk2h((pa2 - ha2) * PSC, (pa3 - ha3) * PSC);
                pl[2] = pk2h((pb0 - hb0) * PSC, (pb1 - hb1) * PSC);
                pl[3] = pk2h((pb2 - hb2) * PSC, (pb3 - hb3) * PSC);
            }
#pragma unroll
            for (int vg = 0; vg < 2; vg++) {
                uint32_t vh[4];
                const uint32_t kr = (uint32_t)(kt * 16 + ((lane >> 3) & 1) * 8 + (lane & 7));
                const uint32_t cb = (uint32_t)(vg * 32 + (lane >> 4) * 16);
                LDSM_X4T(vh, hb + AVH + kr * 64u + swz64(cb, kr));
#pragma unroll
                for (int nn = 0; nn < 2; nn++) {
                    MMA_FH(O[vg * 2 + nn], ph, vh + nn * 2);
                    MMA_HH(Olo[vg * 2 + nn], pl, vh + nn * 2);
                }
            }
        }

        {
#pragma unroll
            for (int nf = 0; nf < 4; nf++) {
                const int c = nf * 8 + qc;
                float2 c01 = __half22float2(*(const __half2*)&Olo[nf][0]);
                float2 c23 = __half22float2(*(const __half2*)&Olo[nf][1]);
                if (r0 < NTOK)
                    *(uint32_t*)(obase + (size_t)r0 * DIMF + c) =
                        pk2h(O[nf][0] + c01.x * PSCINV, O[nf][1] + c01.y * PSCINV);
                if (r0 + 8 < NTOK)
                    *(uint32_t*)(obase + (size_t)(r0 + 8) * DIMF + c) =
                        pk2h(O[nf][2] + c23.x * PSCINV, O[nf][3] + c23.y * PSCINV);
            }
        }
    }
}

// =====================================================================
// launch
// =====================================================================
extern "C" void kernel_launch(void* const* d_in, const int* in_sizes, int n_in,
                              void* d_out, int out_size)
{
    const float* x           = (const float*)d_in[0];
    const float* qkv_w       = (const float*)d_in[1];
    const float* qkv_b       = (const float*)d_in[2];
    const float* proj_w      = (const float*)d_in[3];
    const float* proj_b      = (const float*)d_in[4];
    const float* logit_scale = (const float*)d_in[5];
    const float* cpb_w1      = (const float*)d_in[6];
    const float* cpb_b1      = (const float*)d_in[7];
    const float* cpb_w2      = (const float*)d_in[8];
    float* out = (float*)d_out;

    float *qkvbuf, *attnbuf, *biasbuf, *scalebuf;
    unsigned char *wqbuf, *wpbuf;
    cudaGetSymbolAddress((void**)&qkvbuf,   g_qkv);
    cudaGetSymbolAddress((void**)&attnbuf,  g_attn);
    cudaGetSymbolAddress((void**)&biasbuf,  g_bias);
    cudaGetSymbolAddress((void**)&scalebuf, g_scale);
    cudaGetSymbolAddress((void**)&wqbuf,    g_wq);
    cudaGetSymbolAddress((void**)&wpbuf,    g_wp);

    cudaFuncSetAttribute((const void*)gemm_mma<false, true>,
                         cudaFuncAttributeMaxDynamicSharedMemorySize, GEMM_SMEM);
    cudaFuncSetAttribute((const void*)gemm_mma<true, false>,
                         cudaFuncAttributeMaxDynamicSharedMemorySize, GEMM_SMEM);
    cudaFuncSetAttribute((const void*)attn_tc,
                         cudaFuncAttributeMaxDynamicSharedMemorySize, ATTN_SMEM);

    cpb_kernel<<<1, 256>>>(logit_scale, cpb_w1, cpb_b1, cpb_w2, biasbuf, scalebuf);
    wsplit_kernel<<<128, 256>>>(qkv_w, proj_w, wqbuf, wpbuf);

    // QKV: fp16 output intermediate
    gemm_mma<false, true><<<MROWS / 64, 256, GEMM_SMEM>>>(x, wqbuf, qkv_b, qkvbuf, 6);

    attn_tc<<<dim3(B_WIN, 2), 256, ATTN_SMEM>>>((const __half*)qkvbuf, biasbuf,
                                                scalebuf, (__half*)attnbuf);

    // proj: fp16 A input, fp32 output
    gemm_mma<true, false><<<MROWS / 64, 256, GEMM_SMEM>>>(attnbuf, wpbuf, proj_b, out, 2);
}